// round 2
// baseline (speedup 1.0000x reference)
#include <cuda_runtime.h>
#include <math_constants.h>
#include <cstdint>

#define NROWS 8192
#define DDIM  512
#define BI 64
#define BJ 64
#define BK 32
#define IDX_NONE 0x7fffffff

// ---------------- scratch (static device globals; no allocation) ----------------
__device__ float g_unit[NROWS * DDIM];   // 16 MB, L2-resident
__device__ int   g_pos[NROWS];
__device__ int   g_neg[NROWS];
__device__ float g_per[NROWS];
__device__ float g_val[NROWS];

// ---------------- kernel 1: normalize rows ----------------
// grid = NROWS, block = 128 (each thread owns one float4 of the row)
__global__ void normalize_kernel(const float* __restrict__ emb) {
    int row = blockIdx.x;
    int t   = threadIdx.x;
    float4 v = ((const float4*)(emb + (size_t)row * DDIM))[t];
    float s = v.x * v.x + v.y * v.y + v.z * v.z + v.w * v.w;
    #pragma unroll
    for (int o = 16; o; o >>= 1) s += __shfl_down_sync(0xffffffffu, s, o);
    __shared__ float ws[4];
    if ((t & 31) == 0) ws[t >> 5] = s;
    __syncthreads();
    float tot = ws[0] + ws[1] + ws[2] + ws[3];
    float inv = 1.0f / fmaxf(sqrtf(tot), 1e-8f);
    float4 u = make_float4(v.x * inv, v.y * inv, v.z * inv, v.w * inv);
    ((float4*)(g_unit + (size_t)row * DDIM))[t] = u;
}

// ---------------- kernel 2: fused Gram matrix + hard mining ----------------
// grid = NROWS/BI = 128 blocks, 256 threads (16x16), 4x4 register tile.
// dist = 1 - dot  =>  hardest positive = MIN dot (same label, j != i),
//                     hardest negative = MAX dot (diff label).
// Ties broken by smallest index (matches jnp.argmax/argmin first-occurrence).
__global__ void mine_kernel(const int* __restrict__ labels) {
    __shared__ float As[BK][BI];
    __shared__ float Bs[BK][BJ];
    __shared__ int   lblI[BI];
    __shared__ int   lblJ[BJ];
    __shared__ float sPD[BI]; __shared__ int sPI[BI];
    __shared__ float sND[BI]; __shared__ int sNI[BI];

    int tid = threadIdx.x;
    int tx  = tid & 15;
    int ty  = tid >> 4;
    int i0  = blockIdx.x * BI;

    if (tid < BI) {
        lblI[tid] = labels[i0 + tid];
        sPD[tid]  =  CUDART_INF_F; sPI[tid] = IDX_NONE;
        sND[tid]  = -CUDART_INF_F; sNI[tid] = IDX_NONE;
    }
    __syncthreads();

    for (int j0 = 0; j0 < NROWS; j0 += BJ) {
        if (tid < BJ) lblJ[tid] = labels[j0 + tid];

        float acc[4][4];
        #pragma unroll
        for (int a = 0; a < 4; a++)
            #pragma unroll
            for (int b = 0; b < 4; b++) acc[a][b] = 0.0f;

        for (int k0 = 0; k0 < DDIM; k0 += BK) {
            // load A tile (64 rows x 32 k) and B tile, k-major in smem
            #pragma unroll
            for (int l = 0; l < 8; l++) {
                int e = tid + l * 256;
                int i = e >> 5;       // 0..63
                int k = e & 31;       // 0..31
                As[k][i] = g_unit[(size_t)(i0 + i) * DDIM + k0 + k];
                Bs[k][i] = g_unit[(size_t)(j0 + i) * DDIM + k0 + k];
            }
            __syncthreads();
            #pragma unroll
            for (int k = 0; k < BK; k++) {
                float4 av = *(const float4*)&As[k][ty << 2];
                float4 bv = *(const float4*)&Bs[k][tx << 2];
                float a_[4] = {av.x, av.y, av.z, av.w};
                float b_[4] = {bv.x, bv.y, bv.z, bv.w};
                #pragma unroll
                for (int s = 0; s < 4; s++)
                    #pragma unroll
                    for (int t = 0; t < 4; t++)
                        acc[s][t] = fmaf(a_[s], b_[t], acc[s][t]);
            }
            __syncthreads();
        }

        // masked selection for this 64x64 tile
        #pragma unroll
        for (int s = 0; s < 4; s++) {
            int r   = (ty << 2) + s;
            int gi  = i0 + r;
            int lbl = lblI[r];
            float pd =  CUDART_INF_F; int pi = IDX_NONE;
            float nd = -CUDART_INF_F; int ni = IDX_NONE;
            #pragma unroll
            for (int t = 0; t < 4; t++) {
                int   jc = (tx << 2) + t;
                int   j  = j0 + jc;
                float d  = acc[s][t];
                int   lj = lblJ[jc];
                if (lj == lbl) {
                    if (j != gi) {
                        if (d < pd || (d == pd && j < pi)) { pd = d; pi = j; }
                    }
                } else {
                    if (d > nd || (d == nd && j < ni)) { nd = d; ni = j; }
                }
            }
            // reduce across the 16 threads of this row group (lanes are a
            // contiguous 16-lane half-warp: tid = ty*16 + tx)
            #pragma unroll
            for (int off = 8; off; off >>= 1) {
                float opd = __shfl_down_sync(0xffffffffu, pd, off, 16);
                int   opi = __shfl_down_sync(0xffffffffu, pi, off, 16);
                float ond = __shfl_down_sync(0xffffffffu, nd, off, 16);
                int   oni = __shfl_down_sync(0xffffffffu, ni, off, 16);
                if (opd < pd || (opd == pd && opi < pi)) { pd = opd; pi = opi; }
                if (ond > nd || (ond == nd && oni < ni)) { nd = ond; ni = oni; }
            }
            if (tx == 0) {
                if (pd < sPD[r] || (pd == sPD[r] && pi < sPI[r])) { sPD[r] = pd; sPI[r] = pi; }
                if (nd > sND[r] || (nd == sND[r] && ni < sNI[r])) { sND[r] = nd; sNI[r] = ni; }
            }
        }
        __syncthreads();  // protect lblJ / best arrays before next tile
    }

    if (tid < BI) {
        g_pos[i0 + tid] = sPI[tid];
        g_neg[i0 + tid] = sNI[tid];
    }
}

// ---------------- kernel 3: per-row triplet loss ----------------
// grid = NROWS, block = 128
__global__ void triplet_kernel(const float* __restrict__ emb) {
    int i = blockIdx.x;
    int t = threadIdx.x;
    int pi = g_pos[i];
    int ni = g_neg[i];
    bool valid = (pi != IDX_NONE) && (ni != IDX_NONE);
    if (!valid) {
        if (t == 0) { g_per[i] = 0.0f; g_val[i] = 0.0f; }
        return;
    }
    float4 av = ((const float4*)(emb + (size_t)i  * DDIM))[t];
    float4 pv = ((const float4*)(emb + (size_t)pi * DDIM))[t];
    float4 nv = ((const float4*)(emb + (size_t)ni * DDIM))[t];

    float sap = 0.0f, san = 0.0f, d;
    d = av.x - pv.x + 1e-6f; sap += d * d;
    d = av.y - pv.y + 1e-6f; sap += d * d;
    d = av.z - pv.z + 1e-6f; sap += d * d;
    d = av.w - pv.w + 1e-6f; sap += d * d;
    d = av.x - nv.x + 1e-6f; san += d * d;
    d = av.y - nv.y + 1e-6f; san += d * d;
    d = av.z - nv.z + 1e-6f; san += d * d;
    d = av.w - nv.w + 1e-6f; san += d * d;

    #pragma unroll
    for (int o = 16; o; o >>= 1) {
        sap += __shfl_down_sync(0xffffffffu, sap, o);
        san += __shfl_down_sync(0xffffffffu, san, o);
    }
    __shared__ float wp[4], wn[4];
    if ((t & 31) == 0) { wp[t >> 5] = sap; wn[t >> 5] = san; }
    __syncthreads();
    if (t == 0) {
        float tp = wp[0] + wp[1] + wp[2] + wp[3];
        float tn = wn[0] + wn[1] + wn[2] + wn[3];
        float l  = sqrtf(tp) - sqrtf(tn) + 1.0f;   // margin = 1.0
        g_per[i] = fmaxf(l, 0.0f);
        g_val[i] = 1.0f;
    }
}

// ---------------- kernel 4: deterministic final reduction ----------------
// single block, 256 threads
__global__ void reduce_kernel(float* __restrict__ out) {
    int t = threadIdx.x;
    float s = 0.0f, c = 0.0f;
    for (int i = t; i < NROWS; i += 256) { s += g_per[i]; c += g_val[i]; }
    #pragma unroll
    for (int o = 16; o; o >>= 1) {
        s += __shfl_down_sync(0xffffffffu, s, o);
        c += __shfl_down_sync(0xffffffffu, c, o);
    }
    __shared__ float ss[8], sc[8];
    if ((t & 31) == 0) { ss[t >> 5] = s; sc[t >> 5] = c; }
    __syncthreads();
    if (t < 8) {
        s = ss[t]; c = sc[t];
        #pragma unroll
        for (int o = 4; o; o >>= 1) {
            s += __shfl_down_sync(0xffu, s, o, 8);
            c += __shfl_down_sync(0xffu, c, o, 8);
        }
        if (t == 0) out[0] = s / fmaxf(c, 1.0f);
    }
}

// ---------------- launch ----------------
extern "C" void kernel_launch(void* const* d_in, const int* in_sizes, int n_in,
                              void* d_out, int out_size) {
    const float* emb    = (const float*)d_in[0];
    const int*   labels = (const int*)d_in[1];
    float*       out    = (float*)d_out;

    normalize_kernel<<<NROWS, 128>>>(emb);
    mine_kernel<<<NROWS / BI, 256>>>(labels);
    triplet_kernel<<<NROWS, 128>>>(emb);
    reduce_kernel<<<1, 256>>>(out);
}

// round 5
// speedup vs baseline: 9.2920x; 9.2920x over previous
#include <cuda_runtime.h>
#include <math_constants.h>
#include <cstdint>

#define NROWS 8192
#define DDIM  512
#define IDX_NONE 0x7fffffff

#define JSPLIT 2
#define MTILE 128
#define NTILE 128
#define BK 16
#define NSTAGES (DDIM / BK)               // 32
#define NJT (NROWS / NTILE)               // 64
#define TILES_PER_SPLIT (NJT / JSPLIT)    // 32
#define SMS 20                            // smem row stride in floats (16 + 4 pad)

// ---------------- scratch ----------------
__device__ float g_unit[NROWS * DDIM];    // tf32-rounded unit vectors
__device__ float g_pPD[JSPLIT * NROWS];
__device__ int   g_pPI[JSPLIT * NROWS];
__device__ float g_pND[JSPLIT * NROWS];
__device__ int   g_pNI[JSPLIT * NROWS];
__device__ float g_per[NROWS];
__device__ float g_val[NROWS];

// ---------------- helpers ----------------
__device__ __forceinline__ uint32_t smem_u32(const void* p) {
    uint32_t a;
    asm("{ .reg .u64 t; cvta.to.shared.u64 t, %1; cvt.u32.u64 %0, t; }"
        : "=r"(a) : "l"(p));
    return a;
}

__device__ __forceinline__ void cp16(uint32_t dst, const float* src) {
    asm volatile("cp.async.cg.shared.global [%0], [%1], 16;"
                 :: "r"(dst), "l"(src));
}
#define CP_COMMIT() asm volatile("cp.async.commit_group;" ::: "memory")
#define CP_WAIT(n)  asm volatile("cp.async.wait_group %0;" :: "n"(n) : "memory")

// tf32 cvt destination must be a .b32 register operand
__device__ __forceinline__ float to_tf32(float x) {
    uint32_t r;
    asm("cvt.rna.tf32.f32 %0, %1;" : "=r"(r) : "f"(x));
    return __uint_as_float(r);
}

__device__ __forceinline__ void mma_tf32(float* c, const uint32_t* a,
                                         uint32_t b0, uint32_t b1) {
    asm volatile(
        "mma.sync.aligned.m16n8k8.row.col.f32.tf32.tf32.f32 "
        "{%0,%1,%2,%3}, {%4,%5,%6,%7}, {%8,%9}, {%0,%1,%2,%3};"
        : "+f"(c[0]), "+f"(c[1]), "+f"(c[2]), "+f"(c[3])
        : "r"(a[0]), "r"(a[1]), "r"(a[2]), "r"(a[3]), "r"(b0), "r"(b1));
}

// ---------------- kernel 1: normalize rows (+ tf32 round) ----------------
__global__ void normalize_kernel(const float* __restrict__ emb) {
    int row = blockIdx.x;
    int t   = threadIdx.x;
    float4 v = ((const float4*)(emb + (size_t)row * DDIM))[t];
    float s = v.x * v.x + v.y * v.y + v.z * v.z + v.w * v.w;
    #pragma unroll
    for (int o = 16; o; o >>= 1) s += __shfl_down_sync(0xffffffffu, s, o);
    __shared__ float ws[4];
    if ((t & 31) == 0) ws[t >> 5] = s;
    __syncthreads();
    float tot = ws[0] + ws[1] + ws[2] + ws[3];
    float inv = 1.0f / fmaxf(sqrtf(tot), 1e-8f);
    ((float4*)(g_unit + (size_t)row * DDIM))[t] =
        make_float4(to_tf32(v.x * inv), to_tf32(v.y * inv),
                    to_tf32(v.z * inv), to_tf32(v.w * inv));
}

// ---------------- kernel 2: tf32 mma.sync Gram + hard mining ----------------
// grid = (64, JSPLIT), 256 threads (8 warps, 4x2). CTA tile 128x128.
// dist = 1 - dot: hardest positive = MIN dot (same label, j!=i),
//                 hardest negative = MAX dot (diff label). Ties -> smallest j.
__global__ void __launch_bounds__(256, 1)
mine_kernel(const int* __restrict__ labels) {
    __shared__ float As[2][MTILE * SMS];
    __shared__ float Bs[2][NTILE * SMS];
    __shared__ float candPD[2][128]; __shared__ int candPI[2][128];
    __shared__ float candND[2][128]; __shared__ int candNI[2][128];
    __shared__ float runPD[128];     __shared__ int runPI[128];
    __shared__ float runND[128];     __shared__ int runNI[128];
    __shared__ int   lblI[128];      __shared__ int lblJ[128];

    const int tid  = threadIdx.x;
    const int lane = tid & 31;
    const int wid  = tid >> 5;
    const int gid  = lane >> 2;     // 0..7
    const int tig  = lane & 3;      // 0..3
    const int wr   = wid >> 1;      // 0..3  (row band: wr*32)
    const int wc   = wid & 1;       // 0..1  (col band: wc*64)
    const int i0   = blockIdx.x * MTILE;
    const int sp   = blockIdx.y;

    if (tid < 128) {
        lblI[tid]  = labels[i0 + tid];
        runPD[tid] =  CUDART_INF_F; runPI[tid] = IDX_NONE;
        runND[tid] = -CUDART_INF_F; runNI[tid] = IDX_NONE;
    }
    __syncthreads();

    const uint32_t asb0 = smem_u32(As[0]);
    const uint32_t asb1 = smem_u32(As[1]);
    const uint32_t bsb0 = smem_u32(Bs[0]);
    const uint32_t bsb1 = smem_u32(Bs[1]);

    for (int t = 0; t < TILES_PER_SPLIT; t++) {
        const int j0 = (sp + t * JSPLIT) * NTILE;
        if (tid < 128) lblJ[tid] = labels[j0 + tid];

        float acc[2][8][4];
        #pragma unroll
        for (int mi = 0; mi < 2; mi++)
            #pragma unroll
            for (int ni = 0; ni < 8; ni++)
                #pragma unroll
                for (int q = 0; q < 4; q++) acc[mi][ni][q] = 0.0f;

        // ---- prologue: stage 0 ----
        {
            const int k0 = 0;
            #pragma unroll
            for (int it = 0; it < 2; it++) {
                int idx = tid + it * 256;
                int row = idx >> 2, c = idx & 3;
                uint32_t off = (uint32_t)(row * SMS + c * 4) * 4u;
                cp16(asb0 + off, g_unit + (size_t)(i0 + row) * DDIM + k0 + c * 4);
                cp16(bsb0 + off, g_unit + (size_t)(j0 + row) * DDIM + k0 + c * 4);
            }
            CP_COMMIT();
        }

        for (int s = 0; s < NSTAGES; s++) {
            if (s + 1 < NSTAGES) {
                const int k0 = (s + 1) * BK;
                const uint32_t ab = ((s + 1) & 1) ? asb1 : asb0;
                const uint32_t bb = ((s + 1) & 1) ? bsb1 : bsb0;
                #pragma unroll
                for (int it = 0; it < 2; it++) {
                    int idx = tid + it * 256;
                    int row = idx >> 2, c = idx & 3;
                    uint32_t off = (uint32_t)(row * SMS + c * 4) * 4u;
                    cp16(ab + off, g_unit + (size_t)(i0 + row) * DDIM + k0 + c * 4);
                    cp16(bb + off, g_unit + (size_t)(j0 + row) * DDIM + k0 + c * 4);
                }
                CP_COMMIT();
                CP_WAIT(1);
            } else {
                CP_WAIT(0);
            }
            __syncthreads();

            const float* A = As[s & 1];
            const float* B = Bs[s & 1];
            #pragma unroll
            for (int kk = 0; kk < 2; kk++) {
                const int ko = kk * 8;
                uint32_t a[2][4];
                #pragma unroll
                for (int mi = 0; mi < 2; mi++) {
                    int r = wr * 32 + mi * 16 + gid;
                    a[mi][0] = __float_as_uint(A[r * SMS + ko + tig]);
                    a[mi][1] = __float_as_uint(A[(r + 8) * SMS + ko + tig]);
                    a[mi][2] = __float_as_uint(A[r * SMS + ko + tig + 4]);
                    a[mi][3] = __float_as_uint(A[(r + 8) * SMS + ko + tig + 4]);
                }
                #pragma unroll
                for (int ni = 0; ni < 8; ni++) {
                    int n = wc * 64 + ni * 8 + gid;
                    uint32_t b0 = __float_as_uint(B[n * SMS + ko + tig]);
                    uint32_t b1 = __float_as_uint(B[n * SMS + ko + tig + 4]);
                    mma_tf32(acc[0][ni], a[0], b0, b1);
                    mma_tf32(acc[1][ni], a[1], b0, b1);
                }
            }
            __syncthreads();
        }

        // ---- selection epilogue for this 128x128 tile ----
        #pragma unroll
        for (int mi = 0; mi < 2; mi++) {
            #pragma unroll
            for (int h = 0; h < 2; h++) {
                int row = wr * 32 + mi * 16 + h * 8 + gid;
                int gi  = i0 + row;
                int lbl = lblI[row];
                float pd =  CUDART_INF_F; int pi = IDX_NONE;
                float nd = -CUDART_INF_F; int ni_ = IDX_NONE;
                #pragma unroll
                for (int ni = 0; ni < 8; ni++) {
                    #pragma unroll
                    for (int u = 0; u < 2; u++) {
                        int jc = wc * 64 + ni * 8 + tig * 2 + u;
                        int j  = j0 + jc;
                        float d = acc[mi][ni][h * 2 + u];
                        int  lj = lblJ[jc];
                        if (lj == lbl) {
                            if (j != gi && d < pd) { pd = d; pi = j; }
                        } else if (d > nd) { nd = d; ni_ = j; }
                    }
                }
                // reduce across the 4 lanes of this group (same row)
                #pragma unroll
                for (int off = 2; off; off >>= 1) {
                    float opd = __shfl_down_sync(0xffffffffu, pd, off, 4);
                    int   opi = __shfl_down_sync(0xffffffffu, pi, off, 4);
                    float ond = __shfl_down_sync(0xffffffffu, nd, off, 4);
                    int   oni = __shfl_down_sync(0xffffffffu, ni_, off, 4);
                    if (opd < pd || (opd == pd && opi < pi)) { pd = opd; pi = opi; }
                    if (ond > nd || (ond == nd && oni < ni_)) { nd = ond; ni_ = oni; }
                }
                if (tig == 0) {
                    candPD[wc][row] = pd; candPI[wc][row] = pi;
                    candND[wc][row] = nd; candNI[wc][row] = ni_;
                }
            }
        }
        __syncthreads();
        if (tid < 128) {
            float pd = runPD[tid]; int pi = runPI[tid];
            float nd = runND[tid]; int ni_ = runNI[tid];
            #pragma unroll
            for (int w = 0; w < 2; w++) {
                float cpd = candPD[w][tid]; int cpi = candPI[w][tid];
                float cnd = candND[w][tid]; int cni = candNI[w][tid];
                if (cpd < pd || (cpd == pd && cpi < pi)) { pd = cpd; pi = cpi; }
                if (cnd > nd || (cnd == nd && cni < ni_)) { nd = cnd; ni_ = cni; }
            }
            runPD[tid] = pd; runPI[tid] = pi;
            runND[tid] = nd; runNI[tid] = ni_;
        }
        __syncthreads();
    }

    if (tid < 128) {
        int o = sp * NROWS + i0 + tid;
        g_pPD[o] = runPD[tid]; g_pPI[o] = runPI[tid];
        g_pND[o] = runND[tid]; g_pNI[o] = runNI[tid];
    }
}

// ---------------- kernel 3: merge splits + per-row triplet loss ----------------
__global__ void triplet_kernel(const float* __restrict__ emb) {
    int i = blockIdx.x;
    int t = threadIdx.x;

    __shared__ int spi, sni;
    __shared__ bool svalid;
    if (t == 0) {
        float pd = g_pPD[i];          int pi = g_pPI[i];
        float nd = g_pND[i];          int ni = g_pNI[i];
        float pd1 = g_pPD[NROWS + i]; int pi1 = g_pPI[NROWS + i];
        float nd1 = g_pND[NROWS + i]; int ni1 = g_pNI[NROWS + i];
        if (pd1 < pd || (pd1 == pd && pi1 < pi)) { pd = pd1; pi = pi1; }
        if (nd1 > nd || (nd1 == nd && ni1 < ni)) { nd = nd1; ni = ni1; }
        spi = pi; sni = ni;
        svalid = (pi != IDX_NONE) && (ni != IDX_NONE);
    }
    __syncthreads();
    if (!svalid) {
        if (t == 0) { g_per[i] = 0.0f; g_val[i] = 0.0f; }
        return;
    }
    int pi = spi, ni = sni;
    float4 av = ((const float4*)(emb + (size_t)i  * DDIM))[t];
    float4 pv = ((const float4*)(emb + (size_t)pi * DDIM))[t];
    float4 nv = ((const float4*)(emb + (size_t)ni * DDIM))[t];

    float sap = 0.0f, san = 0.0f, d;
    d = av.x - pv.x + 1e-6f; sap += d * d;
    d = av.y - pv.y + 1e-6f; sap += d * d;
    d = av.z - pv.z + 1e-6f; sap += d * d;
    d = av.w - pv.w + 1e-6f; sap += d * d;
    d = av.x - nv.x + 1e-6f; san += d * d;
    d = av.y - nv.y + 1e-6f; san += d * d;
    d = av.z - nv.z + 1e-6f; san += d * d;
    d = av.w - nv.w + 1e-6f; san += d * d;

    #pragma unroll
    for (int o = 16; o; o >>= 1) {
        sap += __shfl_down_sync(0xffffffffu, sap, o);
        san += __shfl_down_sync(0xffffffffu, san, o);
    }
    __shared__ float wp[4], wn[4];
    if ((t & 31) == 0) { wp[t >> 5] = sap; wn[t >> 5] = san; }
    __syncthreads();
    if (t == 0) {
        float tp = wp[0] + wp[1] + wp[2] + wp[3];
        float tn = wn[0] + wn[1] + wn[2] + wn[3];
        float l  = sqrtf(tp) - sqrtf(tn) + 1.0f;   // margin = 1.0
        g_per[i] = fmaxf(l, 0.0f);
        g_val[i] = 1.0f;
    }
}

// ---------------- kernel 4: deterministic final reduction ----------------
__global__ void reduce_kernel(float* __restrict__ out) {
    int t = threadIdx.x;
    float s = 0.0f, c = 0.0f;
    for (int i = t; i < NROWS; i += 256) { s += g_per[i]; c += g_val[i]; }
    #pragma unroll
    for (int o = 16; o; o >>= 1) {
        s += __shfl_down_sync(0xffffffffu, s, o);
        c += __shfl_down_sync(0xffffffffu, c, o);
    }
    __shared__ float ss[8], sc[8];
    if ((t & 31) == 0) { ss[t >> 5] = s; sc[t >> 5] = c; }
    __syncthreads();
    if (t < 8) {
        s = ss[t]; c = sc[t];
        #pragma unroll
        for (int o = 4; o; o >>= 1) {
            s += __shfl_down_sync(0xffu, s, o, 8);
            c += __shfl_down_sync(0xffu, c, o, 8);
        }
        if (t == 0) out[0] = s / fmaxf(c, 1.0f);
    }
}

// ---------------- launch ----------------
extern "C" void kernel_launch(void* const* d_in, const int* in_sizes, int n_in,
                              void* d_out, int out_size) {
    const float* emb    = (const float*)d_in[0];
    const int*   labels = (const int*)d_in[1];
    float*       out    = (float*)d_out;

    normalize_kernel<<<NROWS, 128>>>(emb);
    mine_kernel<<<dim3(NROWS / MTILE, JSPLIT), 256>>>(labels);
    triplet_kernel<<<NROWS, 128>>>(emb);
    reduce_kernel<<<1, 256>>>(out);
}

// round 6
// speedup vs baseline: 12.9788x; 1.3968x over previous
#include <cuda_runtime.h>
#include <math_constants.h>
#include <cstdint>

#define NROWS 8192
#define DDIM  512
#define MTILE 128
#define NTILE 128
#define BK 16
#define NSTAGES (DDIM / BK)               // 32
#define NBANDS (NROWS / NTILE)            // 64
#define SMS 20                            // smem row stride in floats (16 + 4 pad)

typedef unsigned long long u64;
#define KPOS_INIT 0xFFFFFFFFFFFFFFFFull
#define KNEG_INIT 0ull

// ---------------- scratch ----------------
__device__ float g_unit[NROWS * DDIM];    // tf32-rounded unit vectors
__device__ u64   g_posKey[NROWS];         // min over (ord(dot)<<32 | j)
__device__ u64   g_negKey[NROWS];         // max over (ord(dot)<<32 | (~0u - j))
__device__ float g_per[NROWS];
__device__ float g_val[NROWS];

// ---------------- helpers ----------------
__device__ __forceinline__ uint32_t smem_u32(const void* p) {
    uint32_t a;
    asm("{ .reg .u64 t; cvta.to.shared.u64 t, %1; cvt.u32.u64 %0, t; }"
        : "=r"(a) : "l"(p));
    return a;
}

__device__ __forceinline__ void cp16(uint32_t dst, const float* src) {
    asm volatile("cp.async.cg.shared.global [%0], [%1], 16;"
                 :: "r"(dst), "l"(src));
}
#define CP_COMMIT() asm volatile("cp.async.commit_group;" ::: "memory")
#define CP_WAIT(n)  asm volatile("cp.async.wait_group %0;" :: "n"(n) : "memory")

__device__ __forceinline__ float to_tf32(float x) {
    uint32_t r;
    asm("cvt.rna.tf32.f32 %0, %1;" : "=r"(r) : "f"(x));
    return __uint_as_float(r);
}

// monotonic float -> uint mapping
__device__ __forceinline__ uint32_t ford(float f) {
    uint32_t u = __float_as_uint(f);
    return u ^ (uint32_t)(((int32_t)u >> 31) | 0x80000000);
}

__device__ __forceinline__ void mma_tf32(float* c, const uint32_t* a,
                                         uint32_t b0, uint32_t b1) {
    asm volatile(
        "mma.sync.aligned.m16n8k8.row.col.f32.tf32.tf32.f32 "
        "{%0,%1,%2,%3}, {%4,%5,%6,%7}, {%8,%9}, {%0,%1,%2,%3};"
        : "+f"(c[0]), "+f"(c[1]), "+f"(c[2]), "+f"(c[3])
        : "r"(a[0]), "r"(a[1]), "r"(a[2]), "r"(a[3]), "r"(b0), "r"(b1));
}

// ---------------- kernel 0: reset global keys (graph-replay safe) ----------------
__global__ void init_kernel() {
    int i = blockIdx.x * blockDim.x + threadIdx.x;
    g_posKey[i] = KPOS_INIT;
    g_negKey[i] = KNEG_INIT;
}

// ---------------- kernel 1: normalize rows (+ tf32 round) ----------------
__global__ void normalize_kernel(const float* __restrict__ emb) {
    int row = blockIdx.x;
    int t   = threadIdx.x;
    float4 v = ((const float4*)(emb + (size_t)row * DDIM))[t];
    float s = v.x * v.x + v.y * v.y + v.z * v.z + v.w * v.w;
    #pragma unroll
    for (int o = 16; o; o >>= 1) s += __shfl_down_sync(0xffffffffu, s, o);
    __shared__ float ws[4];
    if ((t & 31) == 0) ws[t >> 5] = s;
    __syncthreads();
    float tot = ws[0] + ws[1] + ws[2] + ws[3];
    float inv = 1.0f / fmaxf(sqrtf(tot), 1e-8f);
    ((float4*)(g_unit + (size_t)row * DDIM))[t] =
        make_float4(to_tf32(v.x * inv), to_tf32(v.y * inv),
                    to_tf32(v.z * inv), to_tf32(v.w * inv));
}

// ---------------- kernel 2: symmetric tf32 Gram + hard mining ----------------
// 128 CTAs: band c2 = blockIdx>>1, half = blockIdx&1. Tiles (c2, (c2+d)%64)
// for d in [0..16] (half 0) / [17..32 or 31] (half 1). Each 128x128 tile
// updates BOTH its row band (locally) and column band (via global atomics).
__global__ void __launch_bounds__(256, 1)
mine_kernel(const int* __restrict__ labels) {
    __shared__ float As[2][MTILE * SMS];
    __shared__ float Bs[2][NTILE * SMS];
    __shared__ u64 rowPos[128], rowNeg[128];
    __shared__ u64 colPos[128], colNeg[128];
    __shared__ int lblJ[128];

    const int tid  = threadIdx.x;
    const int lane = tid & 31;
    const int wid  = tid >> 5;
    const int gid  = lane >> 2;     // 0..7
    const int tig  = lane & 3;      // 0..3
    const int wr   = wid >> 1;      // 0..3 (row band: wr*32)
    const int wc   = wid & 1;       // 0..1 (col band: wc*64)
    const int c2   = blockIdx.x >> 1;
    const int half = blockIdx.x & 1;
    const int i0   = c2 * MTILE;

    const int dBeg = half ? 17 : 0;
    const int dEnd = half ? (c2 < 32 ? 32 : 31) : 16;

    // this thread's 4 row labels (row band fixed for whole CTA)
    int myLbl[2][2];
    #pragma unroll
    for (int mi = 0; mi < 2; mi++)
        #pragma unroll
        for (int h = 0; h < 2; h++)
            myLbl[mi][h] = labels[i0 + wr * 32 + mi * 16 + h * 8 + gid];

    if (tid < 128) {
        rowPos[tid] = KPOS_INIT; rowNeg[tid] = KNEG_INIT;
        colPos[tid] = KPOS_INIT; colNeg[tid] = KNEG_INIT;
    }
    __syncthreads();

    const uint32_t asb0 = smem_u32(As[0]);
    const uint32_t asb1 = smem_u32(As[1]);
    const uint32_t bsb0 = smem_u32(Bs[0]);
    const uint32_t bsb1 = smem_u32(Bs[1]);

    for (int d = dBeg; d <= dEnd; d++) {
        const int bj = (c2 + d) & (NBANDS - 1);
        const int j0 = bj * NTILE;
        if (tid < 128) lblJ[tid] = labels[j0 + tid];

        float acc[2][8][4];
        #pragma unroll
        for (int mi = 0; mi < 2; mi++)
            #pragma unroll
            for (int ni = 0; ni < 8; ni++)
                #pragma unroll
                for (int q = 0; q < 4; q++) acc[mi][ni][q] = 0.0f;

        // prologue: stage 0
        {
            #pragma unroll
            for (int it = 0; it < 2; it++) {
                int idx = tid + it * 256;
                int row = idx >> 2, c = idx & 3;
                uint32_t off = (uint32_t)(row * SMS + c * 4) * 4u;
                cp16(asb0 + off, g_unit + (size_t)(i0 + row) * DDIM + c * 4);
                cp16(bsb0 + off, g_unit + (size_t)(j0 + row) * DDIM + c * 4);
            }
            CP_COMMIT();
        }

        for (int s = 0; s < NSTAGES; s++) {
            if (s + 1 < NSTAGES) {
                const int k0 = (s + 1) * BK;
                const uint32_t ab = ((s + 1) & 1) ? asb1 : asb0;
                const uint32_t bb = ((s + 1) & 1) ? bsb1 : bsb0;
                #pragma unroll
                for (int it = 0; it < 2; it++) {
                    int idx = tid + it * 256;
                    int row = idx >> 2, c = idx & 3;
                    uint32_t off = (uint32_t)(row * SMS + c * 4) * 4u;
                    cp16(ab + off, g_unit + (size_t)(i0 + row) * DDIM + k0 + c * 4);
                    cp16(bb + off, g_unit + (size_t)(j0 + row) * DDIM + k0 + c * 4);
                }
                CP_COMMIT();
                CP_WAIT(1);
            } else {
                CP_WAIT(0);
            }
            __syncthreads();

            const float* A = As[s & 1];
            const float* B = Bs[s & 1];
            #pragma unroll
            for (int kk = 0; kk < 2; kk++) {
                const int ko = kk * 8;
                uint32_t a[2][4];
                #pragma unroll
                for (int mi = 0; mi < 2; mi++) {
                    int r = wr * 32 + mi * 16 + gid;
                    a[mi][0] = __float_as_uint(A[r * SMS + ko + tig]);
                    a[mi][1] = __float_as_uint(A[(r + 8) * SMS + ko + tig]);
                    a[mi][2] = __float_as_uint(A[r * SMS + ko + tig + 4]);
                    a[mi][3] = __float_as_uint(A[(r + 8) * SMS + ko + tig + 4]);
                }
                #pragma unroll
                for (int ni = 0; ni < 8; ni++) {
                    int n = wc * 64 + ni * 8 + gid;
                    uint32_t b0 = __float_as_uint(B[n * SMS + ko + tig]);
                    uint32_t b1 = __float_as_uint(B[n * SMS + ko + tig + 4]);
                    mma_tf32(acc[0][ni], a[0], b0, b1);
                    mma_tf32(acc[1][ni], a[1], b0, b1);
                }
            }
            __syncthreads();
        }

        // ---- row-side selection (rows of band c2) ----
        #pragma unroll
        for (int mi = 0; mi < 2; mi++) {
            #pragma unroll
            for (int h = 0; h < 2; h++) {
                int r   = wr * 32 + mi * 16 + h * 8 + gid;
                int gi  = i0 + r;
                int lbl = myLbl[mi][h];
                u64 pk = KPOS_INIT, nk = KNEG_INIT;
                #pragma unroll
                for (int ni = 0; ni < 8; ni++) {
                    #pragma unroll
                    for (int u = 0; u < 2; u++) {
                        int jc = wc * 64 + ni * 8 + tig * 2 + u;
                        int j  = j0 + jc;
                        u64 od = (u64)ford(acc[mi][ni][h * 2 + u]) << 32;
                        if (lblJ[jc] == lbl) {
                            if (j != gi) {
                                u64 k = od | (uint32_t)j;
                                if (k < pk) pk = k;
                            }
                        } else {
                            u64 k = od | (uint32_t)(0xFFFFFFFFu - j);
                            if (k > nk) nk = k;
                        }
                    }
                }
                #pragma unroll
                for (int off = 2; off; off >>= 1) {
                    u64 opk = __shfl_down_sync(0xffffffffu, pk, off, 4);
                    u64 onk = __shfl_down_sync(0xffffffffu, nk, off, 4);
                    if (opk < pk) pk = opk;
                    if (onk > nk) nk = onk;
                }
                if (tig == 0) {
                    if (pk != KPOS_INIT) atomicMin(&rowPos[r], pk);
                    if (nk != KNEG_INIT) atomicMax(&rowNeg[r], nk);
                }
            }
        }

        // ---- column-side selection (rows of band bj, via transpose) ----
        #pragma unroll
        for (int ni = 0; ni < 8; ni++) {
            #pragma unroll
            for (int u = 0; u < 2; u++) {
                int jc = wc * 64 + ni * 8 + tig * 2 + u;
                int gj = j0 + jc;
                int lj = lblJ[jc];
                u64 pk = KPOS_INIT, nk = KNEG_INIT;
                #pragma unroll
                for (int mi = 0; mi < 2; mi++) {
                    #pragma unroll
                    for (int h = 0; h < 2; h++) {
                        int gi = i0 + wr * 32 + mi * 16 + h * 8 + gid;
                        u64 od = (u64)ford(acc[mi][ni][h * 2 + u]) << 32;
                        if (myLbl[mi][h] == lj) {
                            if (gi != gj) {
                                u64 k = od | (uint32_t)gi;
                                if (k < pk) pk = k;
                            }
                        } else {
                            u64 k = od | (uint32_t)(0xFFFFFFFFu - gi);
                            if (k > nk) nk = k;
                        }
                    }
                }
                #pragma unroll
                for (int off = 16; off >= 4; off >>= 1) {
                    u64 opk = __shfl_down_sync(0xffffffffu, pk, off);
                    u64 onk = __shfl_down_sync(0xffffffffu, nk, off);
                    if (opk < pk) pk = opk;
                    if (onk > nk) nk = onk;
                }
                if (gid == 0) {
                    if (pk != KPOS_INIT) atomicMin(&colPos[jc], pk);
                    if (nk != KNEG_INIT) atomicMax(&colNeg[jc], nk);
                }
            }
        }
        __syncthreads();

        // flush column results to band bj (thread t owns element t; reset after read)
        if (tid < 128) {
            u64 p = colPos[tid], n = colNeg[tid];
            if (p != KPOS_INIT) atomicMin(&g_posKey[j0 + tid], p);
            if (n != KNEG_INIT) atomicMax(&g_negKey[j0 + tid], n);
            colPos[tid] = KPOS_INIT; colNeg[tid] = KNEG_INIT;
        }
        __syncthreads();
    }

    // final row flush for band c2
    if (tid < 128) {
        u64 p = rowPos[tid], n = rowNeg[tid];
        if (p != KPOS_INIT) atomicMin(&g_posKey[i0 + tid], p);
        if (n != KNEG_INIT) atomicMax(&g_negKey[i0 + tid], n);
    }
}

// ---------------- kernel 3: per-row triplet loss ----------------
__global__ void triplet_kernel(const float* __restrict__ emb) {
    int i = blockIdx.x;
    int t = threadIdx.x;

    __shared__ int spi, sni;
    __shared__ bool svalid;
    if (t == 0) {
        u64 pk = g_posKey[i];
        u64 nk = g_negKey[i];
        bool v = (pk != KPOS_INIT) && (nk != KNEG_INIT);
        spi = (int)(uint32_t)(pk & 0xFFFFFFFFull);
        sni = (int)(0xFFFFFFFFu - (uint32_t)(nk & 0xFFFFFFFFull));
        svalid = v;
    }
    __syncthreads();
    if (!svalid) {
        if (t == 0) { g_per[i] = 0.0f; g_val[i] = 0.0f; }
        return;
    }
    int pi = spi, ni = sni;
    float4 av = ((const float4*)(emb + (size_t)i  * DDIM))[t];
    float4 pv = ((const float4*)(emb + (size_t)pi * DDIM))[t];
    float4 nv = ((const float4*)(emb + (size_t)ni * DDIM))[t];

    float sap = 0.0f, san = 0.0f, d;
    d = av.x - pv.x + 1e-6f; sap += d * d;
    d = av.y - pv.y + 1e-6f; sap += d * d;
    d = av.z - pv.z + 1e-6f; sap += d * d;
    d = av.w - pv.w + 1e-6f; sap += d * d;
    d = av.x - nv.x + 1e-6f; san += d * d;
    d = av.y - nv.y + 1e-6f; san += d * d;
    d = av.z - nv.z + 1e-6f; san += d * d;
    d = av.w - nv.w + 1e-6f; san += d * d;

    #pragma unroll
    for (int o = 16; o; o >>= 1) {
        sap += __shfl_down_sync(0xffffffffu, sap, o);
        san += __shfl_down_sync(0xffffffffu, san, o);
    }
    __shared__ float wp[4], wn[4];
    if ((t & 31) == 0) { wp[t >> 5] = sap; wn[t >> 5] = san; }
    __syncthreads();
    if (t == 0) {
        float tp = wp[0] + wp[1] + wp[2] + wp[3];
        float tn = wn[0] + wn[1] + wn[2] + wn[3];
        float l  = sqrtf(tp) - sqrtf(tn) + 1.0f;   // margin = 1.0
        g_per[i] = fmaxf(l, 0.0f);
        g_val[i] = 1.0f;
    }
}

// ---------------- kernel 4: deterministic final reduction ----------------
__global__ void reduce_kernel(float* __restrict__ out) {
    int t = threadIdx.x;
    float s = 0.0f, c = 0.0f;
    for (int i = t; i < NROWS; i += 256) { s += g_per[i]; c += g_val[i]; }
    #pragma unroll
    for (int o = 16; o; o >>= 1) {
        s += __shfl_down_sync(0xffffffffu, s, o);
        c += __shfl_down_sync(0xffffffffu, c, o);
    }
    __shared__ float ss[8], sc[8];
    if ((t & 31) == 0) { ss[t >> 5] = s; sc[t >> 5] = c; }
    __syncthreads();
    if (t < 8) {
        s = ss[t]; c = sc[t];
        #pragma unroll
        for (int o = 4; o; o >>= 1) {
            s += __shfl_down_sync(0xffu, s, o, 8);
            c += __shfl_down_sync(0xffu, c, o, 8);
        }
        if (t == 0) out[0] = s / fmaxf(c, 1.0f);
    }
}

// ---------------- launch ----------------
extern "C" void kernel_launch(void* const* d_in, const int* in_sizes, int n_in,
                              void* d_out, int out_size) {
    const float* emb    = (const float*)d_in[0];
    const int*   labels = (const int*)d_in[1];
    float*       out    = (float*)d_out;

    init_kernel<<<NROWS / 512, 512>>>();
    normalize_kernel<<<NROWS, 128>>>(emb);
    mine_kernel<<<2 * NBANDS, 256>>>(labels);
    triplet_kernel<<<NROWS, 128>>>(emb);
    reduce_kernel<<<1, 256>>>(out);
}

// round 8
// speedup vs baseline: 29.0606x; 2.2391x over previous
#include <cuda_runtime.h>
#include <cuda_fp16.h>
#include <math_constants.h>
#include <cstdint>

#define NROWS 8192
#define DDIM  512
#define MTILE 128
#define NTILE 128
#define BKH 32                            // halves per k-stage
#define NSTAGES (DDIM / BKH)              // 16
#define NBANDS (NROWS / NTILE)            // 64
#define SMS 40                            // smem row stride in halves (32 + 8 pad)

typedef unsigned long long u64;
#define KPOS_INIT 0xFFFFFFFFFFFFFFFFull
#define KNEG_INIT 0ull

// ---------------- scratch ----------------
__device__ __half g_unith[NROWS * DDIM];  // fp16 unit vectors (8 MB, L2-resident)
__device__ u64    g_posKey[NROWS];        // min over (ord(dot)<<32 | j)
__device__ u64    g_negKey[NROWS];        // max over (ord(dot)<<32 | (~0u - j))
__device__ float  g_per[NROWS];
__device__ float  g_val[NROWS];

// ---------------- helpers ----------------
__device__ __forceinline__ uint32_t smem_u32(const void* p) {
    uint32_t a;
    asm("{ .reg .u64 t; cvta.to.shared.u64 t, %1; cvt.u32.u64 %0, t; }"
        : "=r"(a) : "l"(p));
    return a;
}

__device__ __forceinline__ void cp16(uint32_t dst, const void* src) {
    asm volatile("cp.async.cg.shared.global [%0], [%1], 16;"
                 :: "r"(dst), "l"(src));
}
#define CP_COMMIT() asm volatile("cp.async.commit_group;" ::: "memory")
#define CP_WAIT(n)  asm volatile("cp.async.wait_group %0;" :: "n"(n) : "memory")

// monotonic float -> uint mapping
__device__ __forceinline__ uint32_t ford(float f) {
    uint32_t u = __float_as_uint(f);
    return u ^ (uint32_t)(((int32_t)u >> 31) | 0x80000000);
}

__device__ __forceinline__ void mma_f16(float* c, const uint32_t* a,
                                        uint32_t b0, uint32_t b1) {
    asm volatile(
        "mma.sync.aligned.m16n8k16.row.col.f32.f16.f16.f32 "
        "{%0,%1,%2,%3}, {%4,%5,%6,%7}, {%8,%9}, {%0,%1,%2,%3};"
        : "+f"(c[0]), "+f"(c[1]), "+f"(c[2]), "+f"(c[3])
        : "r"(a[0]), "r"(a[1]), "r"(a[2]), "r"(a[3]), "r"(b0), "r"(b1));
}

// ---------------- kernel 1: normalize rows -> fp16, init keys ----------------
__global__ void normalize_kernel(const float* __restrict__ emb) {
    int row = blockIdx.x;
    int t   = threadIdx.x;
    float4 v = ((const float4*)(emb + (size_t)row * DDIM))[t];
    float s = v.x * v.x + v.y * v.y + v.z * v.z + v.w * v.w;
    #pragma unroll
    for (int o = 16; o; o >>= 1) s += __shfl_down_sync(0xffffffffu, s, o);
    __shared__ float ws[4];
    if ((t & 31) == 0) ws[t >> 5] = s;
    __syncthreads();
    float tot = ws[0] + ws[1] + ws[2] + ws[3];
    float inv = 1.0f / fmaxf(sqrtf(tot), 1e-8f);
    __half2* dst = (__half2*)(g_unith + (size_t)row * DDIM);
    dst[2 * t]     = __floats2half2_rn(v.x * inv, v.y * inv);
    dst[2 * t + 1] = __floats2half2_rn(v.z * inv, v.w * inv);
    if (t == 0) { g_posKey[row] = KPOS_INIT; g_negKey[row] = KNEG_INIT; }
}

// ---------------- kernel 2: fp16 mma Gram, one 128x128 tile per CTA ----------
// grid (33, 64): bi = blockIdx.y, bj = (bi + d) % 64, d = blockIdx.x.
// Upper-triangle coverage; d==32 duplicates for bi>=32 are skipped.
// Each tile updates BOTH its row band and (transposed) its column band.
__global__ void __launch_bounds__(256)
mine_kernel(const int* __restrict__ labels) {
    __shared__ __half Ah[2][MTILE * SMS];
    __shared__ __half Bh[2][NTILE * SMS];
    __shared__ u64 rowPos[128], rowNeg[128], colPos[128], colNeg[128];
    __shared__ int lblI[128], lblJ[128];

    const int d  = blockIdx.x;
    const int bi = blockIdx.y;
    if (d == 32 && bi >= 32) return;
    const int bj = (bi + d) & (NBANDS - 1);
    const int i0 = bi * MTILE;
    const int j0 = bj * NTILE;

    const int tid  = threadIdx.x;
    const int lane = tid & 31;
    const int wid  = tid >> 5;
    const int gid  = lane >> 2;     // 0..7
    const int tig  = lane & 3;      // 0..3
    const int wr   = wid >> 1;      // 0..3 (row band: wr*32)
    const int wc   = wid & 1;       // 0..1 (col band: wc*64)

    if (tid < 128) {
        lblI[tid] = labels[i0 + tid];
        lblJ[tid] = labels[j0 + tid];
        rowPos[tid] = KPOS_INIT; rowNeg[tid] = KNEG_INIT;
        colPos[tid] = KPOS_INIT; colNeg[tid] = KNEG_INIT;
    }
    __syncthreads();

    int myLbl[2][2];
    #pragma unroll
    for (int mi = 0; mi < 2; mi++)
        #pragma unroll
        for (int h = 0; h < 2; h++)
            myLbl[mi][h] = lblI[wr * 32 + mi * 16 + h * 8 + gid];

    const uint32_t ab0 = smem_u32(Ah[0]);
    const uint32_t ab1 = smem_u32(Ah[1]);
    const uint32_t bb0 = smem_u32(Bh[0]);
    const uint32_t bb1 = smem_u32(Bh[1]);

    float acc[2][8][4];
    #pragma unroll
    for (int mi = 0; mi < 2; mi++)
        #pragma unroll
        for (int ni = 0; ni < 8; ni++)
            #pragma unroll
            for (int q = 0; q < 4; q++) acc[mi][ni][q] = 0.0f;

    // prologue: stage 0
    {
        #pragma unroll
        for (int it = 0; it < 2; it++) {
            int idx = tid + it * 256;
            int row = idx >> 2, c = idx & 3;
            uint32_t off = (uint32_t)(row * SMS + c * 8) * 2u;
            cp16(ab0 + off, g_unith + (size_t)(i0 + row) * DDIM + c * 8);
            cp16(bb0 + off, g_unith + (size_t)(j0 + row) * DDIM + c * 8);
        }
        CP_COMMIT();
    }

    for (int s = 0; s < NSTAGES; s++) {
        if (s + 1 < NSTAGES) {
            const int k0 = (s + 1) * BKH;
            const uint32_t ab = ((s + 1) & 1) ? ab1 : ab0;
            const uint32_t bb = ((s + 1) & 1) ? bb1 : bb0;
            #pragma unroll
            for (int it = 0; it < 2; it++) {
                int idx = tid + it * 256;
                int row = idx >> 2, c = idx & 3;
                uint32_t off = (uint32_t)(row * SMS + c * 8) * 2u;
                cp16(ab + off, g_unith + (size_t)(i0 + row) * DDIM + k0 + c * 8);
                cp16(bb + off, g_unith + (size_t)(j0 + row) * DDIM + k0 + c * 8);
            }
            CP_COMMIT();
            CP_WAIT(1);
        } else {
            CP_WAIT(0);
        }
        __syncthreads();

        const __half* A = Ah[s & 1];
        const __half* B = Bh[s & 1];
        #pragma unroll
        for (int kk = 0; kk < 2; kk++) {
            const int ko = kk * 16;
            uint32_t a[2][4];
            #pragma unroll
            for (int mi = 0; mi < 2; mi++) {
                int r = wr * 32 + mi * 16 + gid;
                a[mi][0] = *(const uint32_t*)&A[r * SMS + ko + tig * 2];
                a[mi][1] = *(const uint32_t*)&A[(r + 8) * SMS + ko + tig * 2];
                a[mi][2] = *(const uint32_t*)&A[r * SMS + ko + 8 + tig * 2];
                a[mi][3] = *(const uint32_t*)&A[(r + 8) * SMS + ko + 8 + tig * 2];
            }
            #pragma unroll
            for (int ni = 0; ni < 8; ni++) {
                int n = wc * 64 + ni * 8 + gid;
                uint32_t b0 = *(const uint32_t*)&B[n * SMS + ko + tig * 2];
                uint32_t b1 = *(const uint32_t*)&B[n * SMS + ko + 8 + tig * 2];
                mma_f16(acc[0][ni], a[0], b0, b1);
                mma_f16(acc[1][ni], a[1], b0, b1);
            }
        }
        __syncthreads();
    }

    // ---- row-side selection (rows of band bi) ----
    #pragma unroll
    for (int mi = 0; mi < 2; mi++) {
        #pragma unroll
        for (int h = 0; h < 2; h++) {
            int r   = wr * 32 + mi * 16 + h * 8 + gid;
            int gi  = i0 + r;
            int lbl = myLbl[mi][h];
            u64 pk = KPOS_INIT, nk = KNEG_INIT;
            #pragma unroll
            for (int ni = 0; ni < 8; ni++) {
                #pragma unroll
                for (int u = 0; u < 2; u++) {
                    int jc = wc * 64 + ni * 8 + tig * 2 + u;
                    int j  = j0 + jc;
                    u64 od = (u64)ford(acc[mi][ni][h * 2 + u]) << 32;
                    if (lblJ[jc] == lbl) {
                        if (j != gi) {
                            u64 k = od | (uint32_t)j;
                            if (k < pk) pk = k;
                        }
                    } else {
                        u64 k = od | (uint32_t)(0xFFFFFFFFu - j);
                        if (k > nk) nk = k;
                    }
                }
            }
            #pragma unroll
            for (int off = 2; off; off >>= 1) {
                u64 opk = __shfl_down_sync(0xffffffffu, pk, off, 4);
                u64 onk = __shfl_down_sync(0xffffffffu, nk, off, 4);
                if (opk < pk) pk = opk;
                if (onk > nk) nk = onk;
            }
            if (tig == 0) {
                if (pk != KPOS_INIT) atomicMin(&rowPos[r], pk);
                if (nk != KNEG_INIT) atomicMax(&rowNeg[r], nk);
            }
        }
    }

    // ---- column-side selection (rows of band bj, via transpose) ----
    #pragma unroll
    for (int ni = 0; ni < 8; ni++) {
        #pragma unroll
        for (int u = 0; u < 2; u++) {
            int jc = wc * 64 + ni * 8 + tig * 2 + u;
            int gj = j0 + jc;
            int lj = lblJ[jc];
            u64 pk = KPOS_INIT, nk = KNEG_INIT;
            #pragma unroll
            for (int mi = 0; mi < 2; mi++) {
                #pragma unroll
                for (int h = 0; h < 2; h++) {
                    int gi = i0 + wr * 32 + mi * 16 + h * 8 + gid;
                    u64 od = (u64)ford(acc[mi][ni][h * 2 + u]) << 32;
                    if (myLbl[mi][h] == lj) {
                        if (gi != gj) {
                            u64 k = od | (uint32_t)gi;
                            if (k < pk) pk = k;
                        }
                    } else {
                        u64 k = od | (uint32_t)(0xFFFFFFFFu - gi);
                        if (k > nk) nk = k;
                    }
                }
            }
            #pragma unroll
            for (int off = 16; off >= 4; off >>= 1) {
                u64 opk = __shfl_down_sync(0xffffffffu, pk, off);
                u64 onk = __shfl_down_sync(0xffffffffu, nk, off);
                if (opk < pk) pk = opk;
                if (onk > nk) nk = onk;
            }
            if (gid == 0) {
                if (pk != KPOS_INIT) atomicMin(&colPos[jc], pk);
                if (nk != KNEG_INIT) atomicMax(&colNeg[jc], nk);
            }
        }
    }
    __syncthreads();

    // ---- flush both bands (min/max idempotent -> diagonal overlap is safe) ----
    if (tid < 128) {
        u64 rp = rowPos[tid], rn = rowNeg[tid];
        u64 cp = colPos[tid], cn = colNeg[tid];
        if (rp != KPOS_INIT) atomicMin(&g_posKey[i0 + tid], rp);
        if (rn != KNEG_INIT) atomicMax(&g_negKey[i0 + tid], rn);
        if (cp != KPOS_INIT) atomicMin(&g_posKey[j0 + tid], cp);
        if (cn != KNEG_INIT) atomicMax(&g_negKey[j0 + tid], cn);
    }
}

// ---------------- kernel 3: per-row triplet loss ----------------
__global__ void triplet_kernel(const float* __restrict__ emb) {
    int i = blockIdx.x;
    int t = threadIdx.x;

    __shared__ int spi, sni;
    __shared__ bool svalid;
    if (t == 0) {
        u64 pk = g_posKey[i];
        u64 nk = g_negKey[i];
        spi = (int)(uint32_t)(pk & 0xFFFFFFFFull);
        sni = (int)(0xFFFFFFFFu - (uint32_t)(nk & 0xFFFFFFFFull));
        svalid = (pk != KPOS_INIT) && (nk != KNEG_INIT);
    }
    __syncthreads();
    if (!svalid) {
        if (t == 0) { g_per[i] = 0.0f; g_val[i] = 0.0f; }
        return;
    }
    int pi = spi, ni = sni;
    float4 av = ((const float4*)(emb + (size_t)i  * DDIM))[t];
    float4 pv = ((const float4*)(emb + (size_t)pi * DDIM))[t];
    float4 nv = ((const float4*)(emb + (size_t)ni * DDIM))[t];

    float sap = 0.0f, san = 0.0f, dd;
    dd = av.x - pv.x + 1e-6f; sap += dd * dd;
    dd = av.y - pv.y + 1e-6f; sap += dd * dd;
    dd = av.z - pv.z + 1e-6f; sap += dd * dd;
    dd = av.w - pv.w + 1e-6f; sap += dd * dd;
    dd = av.x - nv.x + 1e-6f; san += dd * dd;
    dd = av.y - nv.y + 1e-6f; san += dd * dd;
    dd = av.z - nv.z + 1e-6f; san += dd * dd;
    dd = av.w - nv.w + 1e-6f; san += dd * dd;

    #pragma unroll
    for (int o = 16; o; o >>= 1) {
        sap += __shfl_down_sync(0xffffffffu, sap, o);
        san += __shfl_down_sync(0xffffffffu, san, o);
    }
    __shared__ float wp[4], wn[4];
    if ((t & 31) == 0) { wp[t >> 5] = sap; wn[t >> 5] = san; }
    __syncthreads();
    if (t == 0) {
        float tp = wp[0] + wp[1] + wp[2] + wp[3];
        float tn = wn[0] + wn[1] + wn[2] + wn[3];
        float l  = sqrtf(tp) - sqrtf(tn) + 1.0f;   // margin = 1.0
        g_per[i] = fmaxf(l, 0.0f);
        g_val[i] = 1.0f;
    }
}

// ---------------- kernel 4: deterministic final reduction ----------------
__global__ void reduce_kernel(float* __restrict__ out) {
    int t = threadIdx.x;
    float s = 0.0f, c = 0.0f;
    for (int i = t; i < NROWS; i += 256) { s += g_per[i]; c += g_val[i]; }
    #pragma unroll
    for (int o = 16; o; o >>= 1) {
        s += __shfl_down_sync(0xffffffffu, s, o);
        c += __shfl_down_sync(0xffffffffu, c, o);
    }
    __shared__ float ss[8], sc[8];
    if ((t & 31) == 0) { ss[t >> 5] = s; sc[t >> 5] = c; }
    __syncthreads();
    if (t < 8) {
        s = ss[t]; c = sc[t];
        #pragma unroll
        for (int o = 4; o; o >>= 1) {
            s += __shfl_down_sync(0xffu, s, o, 8);
            c += __shfl_down_sync(0xffu, c, o, 8);
        }
        if (t == 0) out[0] = s / fmaxf(c, 1.0f);
    }
}

// ---------------- launch ----------------
extern "C" void kernel_launch(void* const* d_in, const int* in_sizes, int n_in,
                              void* d_out, int out_size) {
    const float* emb    = (const float*)d_in[0];
    const int*   labels = (const int*)d_in[1];
    float*       out    = (float*)d_out;

    normalize_kernel<<<NROWS, 128>>>(emb);
    mine_kernel<<<dim3(33, NBANDS), 256>>>(labels);
    triplet_kernel<<<NROWS, 128>>>(emb);
    reduce_kernel<<<1, 256>>>(out);
}

// round 9
// speedup vs baseline: 29.7770x; 1.0247x over previous
#include <cuda_runtime.h>
#include <cuda_fp16.h>
#include <math_constants.h>
#include <cstdint>

#define NROWS 8192
#define DDIM  512
#define MTILE 128
#define NTILE 128
#define BKH 32                            // halves per k-stage
#define NSTAGES (DDIM / BKH)              // 16
#define NBANDS (NROWS / NTILE)            // 64
#define SMS 40                            // smem row stride in halves (32 + 8 pad)

typedef unsigned long long u64;
#define KPOS_INIT 0xFFFFFFFFFFFFFFFFull
#define KNEG_INIT 0ull

// ---------------- scratch ----------------
__device__ __half g_unith[NROWS * DDIM];  // fp16 unit vectors (8 MB, L2-resident)
__device__ u64    g_posKey[NROWS];        // min over (ord(dot)<<32 | j)
__device__ u64    g_negKey[NROWS];        // max over (ord(dot)<<32 | (~0u - j))
__device__ float  g_per[NROWS];
__device__ float  g_val[NROWS];

// ---------------- helpers ----------------
__device__ __forceinline__ uint32_t smem_u32(const void* p) {
    uint32_t a;
    asm("{ .reg .u64 t; cvta.to.shared.u64 t, %1; cvt.u32.u64 %0, t; }"
        : "=r"(a) : "l"(p));
    return a;
}

__device__ __forceinline__ void cp16(uint32_t dst, const void* src) {
    asm volatile("cp.async.cg.shared.global [%0], [%1], 16;"
                 :: "r"(dst), "l"(src));
}
#define CP_COMMIT() asm volatile("cp.async.commit_group;" ::: "memory")
#define CP_WAIT(n)  asm volatile("cp.async.wait_group %0;" :: "n"(n) : "memory")

__device__ __forceinline__ void ldm_x4(uint32_t* r, uint32_t addr) {
    asm volatile("ldmatrix.sync.aligned.m8n8.x4.shared.b16 {%0,%1,%2,%3}, [%4];"
                 : "=r"(r[0]), "=r"(r[1]), "=r"(r[2]), "=r"(r[3]) : "r"(addr));
}

// monotonic float -> uint mapping
__device__ __forceinline__ uint32_t ford(float f) {
    uint32_t u = __float_as_uint(f);
    return u ^ (uint32_t)(((int32_t)u >> 31) | 0x80000000);
}

__device__ __forceinline__ void mma_f16(float* c, const uint32_t* a,
                                        uint32_t b0, uint32_t b1) {
    asm volatile(
        "mma.sync.aligned.m16n8k16.row.col.f32.f16.f16.f32 "
        "{%0,%1,%2,%3}, {%4,%5,%6,%7}, {%8,%9}, {%0,%1,%2,%3};"
        : "+f"(c[0]), "+f"(c[1]), "+f"(c[2]), "+f"(c[3])
        : "r"(a[0]), "r"(a[1]), "r"(a[2]), "r"(a[3]), "r"(b0), "r"(b1));
}

// ---------------- kernel 1: normalize rows -> fp16, init keys ----------------
__global__ void normalize_kernel(const float* __restrict__ emb) {
    int row = blockIdx.x;
    int t   = threadIdx.x;
    float4 v = ((const float4*)(emb + (size_t)row * DDIM))[t];
    float s = v.x * v.x + v.y * v.y + v.z * v.z + v.w * v.w;
    #pragma unroll
    for (int o = 16; o; o >>= 1) s += __shfl_down_sync(0xffffffffu, s, o);
    __shared__ float ws[4];
    if ((t & 31) == 0) ws[t >> 5] = s;
    __syncthreads();
    float tot = ws[0] + ws[1] + ws[2] + ws[3];
    float inv = 1.0f / fmaxf(sqrtf(tot), 1e-8f);
    __half2* dst = (__half2*)(g_unith + (size_t)row * DDIM);
    dst[2 * t]     = __floats2half2_rn(v.x * inv, v.y * inv);
    dst[2 * t + 1] = __floats2half2_rn(v.z * inv, v.w * inv);
    if (t == 0) { g_posKey[row] = KPOS_INIT; g_negKey[row] = KNEG_INIT; }
}

// ---------------- kernel 2: fp16 mma Gram, one 128x128 tile per CTA ----------
// grid (33, 64): bi = blockIdx.y, bj = (bi + d) % 64, d = blockIdx.x.
// Upper-triangle coverage; d==32 duplicates for bi>=32 are skipped.
// Each tile updates BOTH its row band and (transposed) its column band.
__global__ void __launch_bounds__(256)
mine_kernel(const int* __restrict__ labels) {
    __shared__ __half Ah[2][MTILE * SMS];
    __shared__ __half Bh[2][NTILE * SMS];
    __shared__ u64 rowPos[128], rowNeg[128], colPos[128], colNeg[128];
    __shared__ int lblI[128], lblJ[128];

    const int d  = blockIdx.x;
    const int bi = blockIdx.y;
    if (d == 32 && bi >= 32) return;
    const int bj = (bi + d) & (NBANDS - 1);
    const int i0 = bi * MTILE;
    const int j0 = bj * NTILE;

    const int tid  = threadIdx.x;
    const int lane = tid & 31;
    const int wid  = tid >> 5;
    const int gid  = lane >> 2;     // 0..7
    const int tig  = lane & 3;      // 0..3
    const int wr   = wid >> 1;      // 0..3 (row band: wr*32)
    const int wc   = wid & 1;       // 0..1 (col band: wc*64)

    if (tid < 128) {
        lblI[tid] = labels[i0 + tid];
        lblJ[tid] = labels[j0 + tid];
        rowPos[tid] = KPOS_INIT; rowNeg[tid] = KNEG_INIT;
        colPos[tid] = KPOS_INIT; colNeg[tid] = KNEG_INIT;
    }
    __syncthreads();

    int myLbl[2][2];
    #pragma unroll
    for (int mi = 0; mi < 2; mi++)
        #pragma unroll
        for (int h = 0; h < 2; h++)
            myLbl[mi][h] = lblI[wr * 32 + mi * 16 + h * 8 + gid];

    const uint32_t ab0 = smem_u32(Ah[0]);
    const uint32_t ab1 = smem_u32(Ah[1]);
    const uint32_t bb0 = smem_u32(Bh[0]);
    const uint32_t bb1 = smem_u32(Bh[1]);

    // ldmatrix lane address bases (in halves)
    const int lr = lane & 7;
    // A 16x16 tile for (mi,kk): mats: 0=(r0-7,k0-7) 1=(r8-15,k0-7) 2=(r0-7,k8-15) 3=(r8-15,k8-15)
    const int rowA = wr * 32 + ((lane >> 3) & 1) * 8 + lr;  // + mi*16
    const int kA   = (lane >> 4) * 8;                        // + kk*16
    // B 16n x 16k tile for (ni2,kk): mats: 0=(n0-7,k0-7) 1=(n0-7,k8-15) 2=(n8-15,k0-7) 3=(n8-15,k8-15)
    const int nB   = wc * 64 + (lane >> 4) * 8 + lr;         // + ni2*16
    const int kB   = ((lane >> 3) & 1) * 8;                  // + kk*16

    float acc[2][8][4];
    #pragma unroll
    for (int mi = 0; mi < 2; mi++)
        #pragma unroll
        for (int ni = 0; ni < 8; ni++)
            #pragma unroll
            for (int q = 0; q < 4; q++) acc[mi][ni][q] = 0.0f;

    // prologue: stage 0
    {
        #pragma unroll
        for (int it = 0; it < 2; it++) {
            int idx = tid + it * 256;
            int row = idx >> 2, c = idx & 3;
            uint32_t off = (uint32_t)(row * SMS + c * 8) * 2u;
            cp16(ab0 + off, g_unith + (size_t)(i0 + row) * DDIM + c * 8);
            cp16(bb0 + off, g_unith + (size_t)(j0 + row) * DDIM + c * 8);
        }
        CP_COMMIT();
    }

    for (int s = 0; s < NSTAGES; s++) {
        if (s + 1 < NSTAGES) {
            const int k0 = (s + 1) * BKH;
            const uint32_t ab = ((s + 1) & 1) ? ab1 : ab0;
            const uint32_t bb = ((s + 1) & 1) ? bb1 : bb0;
            #pragma unroll
            for (int it = 0; it < 2; it++) {
                int idx = tid + it * 256;
                int row = idx >> 2, c = idx & 3;
                uint32_t off = (uint32_t)(row * SMS + c * 8) * 2u;
                cp16(ab + off, g_unith + (size_t)(i0 + row) * DDIM + k0 + c * 8);
                cp16(bb + off, g_unith + (size_t)(j0 + row) * DDIM + k0 + c * 8);
            }
            CP_COMMIT();
            CP_WAIT(1);
        } else {
            CP_WAIT(0);
        }
        __syncthreads();

        const uint32_t abase = (s & 1) ? ab1 : ab0;
        const uint32_t bbase = (s & 1) ? bb1 : bb0;
        #pragma unroll
        for (int kk = 0; kk < 2; kk++) {
            uint32_t a0[4], a1[4];
            ldm_x4(a0, abase + (uint32_t)((rowA)      * SMS + kA + kk * 16) * 2u);
            ldm_x4(a1, abase + (uint32_t)((rowA + 16) * SMS + kA + kk * 16) * 2u);
            #pragma unroll
            for (int ni2 = 0; ni2 < 4; ni2++) {
                uint32_t b[4];
                ldm_x4(b, bbase + (uint32_t)((nB + ni2 * 16) * SMS + kB + kk * 16) * 2u);
                mma_f16(acc[0][2 * ni2],     a0, b[0], b[1]);
                mma_f16(acc[0][2 * ni2 + 1], a0, b[2], b[3]);
                mma_f16(acc[1][2 * ni2],     a1, b[0], b[1]);
                mma_f16(acc[1][2 * ni2 + 1], a1, b[2], b[3]);
            }
        }
        __syncthreads();
    }

    // ---- row-side selection (rows of band bi) ----
    #pragma unroll
    for (int mi = 0; mi < 2; mi++) {
        #pragma unroll
        for (int h = 0; h < 2; h++) {
            int r   = wr * 32 + mi * 16 + h * 8 + gid;
            int gi  = i0 + r;
            int lbl = myLbl[mi][h];
            u64 pk = KPOS_INIT, nk = KNEG_INIT;
            #pragma unroll
            for (int ni = 0; ni < 8; ni++) {
                #pragma unroll
                for (int u = 0; u < 2; u++) {
                    int jc = wc * 64 + ni * 8 + tig * 2 + u;
                    int j  = j0 + jc;
                    u64 od = (u64)ford(acc[mi][ni][h * 2 + u]) << 32;
                    if (lblJ[jc] == lbl) {
                        if (j != gi) {
                            u64 k = od | (uint32_t)j;
                            if (k < pk) pk = k;
                        }
                    } else {
                        u64 k = od | (uint32_t)(0xFFFFFFFFu - j);
                        if (k > nk) nk = k;
                    }
                }
            }
            #pragma unroll
            for (int off = 2; off; off >>= 1) {
                u64 opk = __shfl_down_sync(0xffffffffu, pk, off, 4);
                u64 onk = __shfl_down_sync(0xffffffffu, nk, off, 4);
                if (opk < pk) pk = opk;
                if (onk > nk) nk = onk;
            }
            if (tig == 0) {
                if (pk != KPOS_INIT) atomicMin(&rowPos[r], pk);
                if (nk != KNEG_INIT) atomicMax(&rowNeg[r], nk);
            }
        }
    }

    // ---- column-side selection (rows of band bj, via transpose) ----
    #pragma unroll
    for (int ni = 0; ni < 8; ni++) {
        #pragma unroll
        for (int u = 0; u < 2; u++) {
            int jc = wc * 64 + ni * 8 + tig * 2 + u;
            int gj = j0 + jc;
            int lj = lblJ[jc];
            u64 pk = KPOS_INIT, nk = KNEG_INIT;
            #pragma unroll
            for (int mi = 0; mi < 2; mi++) {
                #pragma unroll
                for (int h = 0; h < 2; h++) {
                    int gi = i0 + wr * 32 + mi * 16 + h * 8 + gid;
                    u64 od = (u64)ford(acc[mi][ni][h * 2 + u]) << 32;
                    if (myLbl[mi][h] == lj) {
                        if (gi != gj) {
                            u64 k = od | (uint32_t)gi;
                            if (k < pk) pk = k;
                        }
                    } else {
                        u64 k = od | (uint32_t)(0xFFFFFFFFu - gi);
                        if (k > nk) nk = k;
                    }
                }
            }
            #pragma unroll
            for (int off = 16; off >= 4; off >>= 1) {
                u64 opk = __shfl_down_sync(0xffffffffu, pk, off);
                u64 onk = __shfl_down_sync(0xffffffffu, nk, off);
                if (opk < pk) pk = opk;
                if (onk > nk) nk = onk;
            }
            if (gid == 0) {
                if (pk != KPOS_INIT) atomicMin(&colPos[jc], pk);
                if (nk != KNEG_INIT) atomicMax(&colNeg[jc], nk);
            }
        }
    }
    __syncthreads();

    // ---- flush both bands (min/max idempotent -> diagonal overlap is safe) ----
    if (tid < 128) {
        u64 rp = rowPos[tid], rn = rowNeg[tid];
        u64 cp = colPos[tid], cn = colNeg[tid];
        if (rp != KPOS_INIT) atomicMin(&g_posKey[i0 + tid], rp);
        if (rn != KNEG_INIT) atomicMax(&g_negKey[i0 + tid], rn);
        if (cp != KPOS_INIT) atomicMin(&g_posKey[j0 + tid], cp);
        if (cn != KNEG_INIT) atomicMax(&g_negKey[j0 + tid], cn);
    }
}

// ---------------- kernel 3: per-row triplet loss ----------------
__global__ void triplet_kernel(const float* __restrict__ emb) {
    int i = blockIdx.x;
    int t = threadIdx.x;

    __shared__ int spi, sni;
    __shared__ bool svalid;
    if (t == 0) {
        u64 pk = g_posKey[i];
        u64 nk = g_negKey[i];
        spi = (int)(uint32_t)(pk & 0xFFFFFFFFull);
        sni = (int)(0xFFFFFFFFu - (uint32_t)(nk & 0xFFFFFFFFull));
        svalid = (pk != KPOS_INIT) && (nk != KNEG_INIT);
    }
    __syncthreads();
    if (!svalid) {
        if (t == 0) { g_per[i] = 0.0f; g_val[i] = 0.0f; }
        return;
    }
    int pi = spi, ni = sni;
    float4 av = ((const float4*)(emb + (size_t)i  * DDIM))[t];
    float4 pv = ((const float4*)(emb + (size_t)pi * DDIM))[t];
    float4 nv = ((const float4*)(emb + (size_t)ni * DDIM))[t];

    float sap = 0.0f, san = 0.0f, dd;
    dd = av.x - pv.x + 1e-6f; sap += dd * dd;
    dd = av.y - pv.y + 1e-6f; sap += dd * dd;
    dd = av.z - pv.z + 1e-6f; sap += dd * dd;
    dd = av.w - pv.w + 1e-6f; sap += dd * dd;
    dd = av.x - nv.x + 1e-6f; san += dd * dd;
    dd = av.y - nv.y + 1e-6f; san += dd * dd;
    dd = av.z - nv.z + 1e-6f; san += dd * dd;
    dd = av.w - nv.w + 1e-6f; san += dd * dd;

    #pragma unroll
    for (int o = 16; o; o >>= 1) {
        sap += __shfl_down_sync(0xffffffffu, sap, o);
        san += __shfl_down_sync(0xffffffffu, san, o);
    }
    __shared__ float wp[4], wn[4];
    if ((t & 31) == 0) { wp[t >> 5] = sap; wn[t >> 5] = san; }
    __syncthreads();
    if (t == 0) {
        float tp = wp[0] + wp[1] + wp[2] + wp[3];
        float tn = wn[0] + wn[1] + wn[2] + wn[3];
        float l  = sqrtf(tp) - sqrtf(tn) + 1.0f;   // margin = 1.0
        g_per[i] = fmaxf(l, 0.0f);
        g_val[i] = 1.0f;
    }
}

// ---------------- kernel 4: deterministic final reduction ----------------
__global__ void reduce_kernel(float* __restrict__ out) {
    int t = threadIdx.x;
    float s = 0.0f, c = 0.0f;
    for (int i = t; i < NROWS; i += 256) { s += g_per[i]; c += g_val[i]; }
    #pragma unroll
    for (int o = 16; o; o >>= 1) {
        s += __shfl_down_sync(0xffffffffu, s, o);
        c += __shfl_down_sync(0xffffffffu, c, o);
    }
    __shared__ float ss[8], sc[8];
    if ((t & 31) == 0) { ss[t >> 5] = s; sc[t >> 5] = c; }
    __syncthreads();
    if (t < 8) {
        s = ss[t]; c = sc[t];
        #pragma unroll
        for (int o = 4; o; o >>= 1) {
            s += __shfl_down_sync(0xffu, s, o, 8);
            c += __shfl_down_sync(0xffu, c, o, 8);
        }
        if (t == 0) out[0] = s / fmaxf(c, 1.0f);
    }
}

// ---------------- launch ----------------
extern "C" void kernel_launch(void* const* d_in, const int* in_sizes, int n_in,
                              void* d_out, int out_size) {
    const float* emb    = (const float*)d_in[0];
    const int*   labels = (const int*)d_in[1];
    float*       out    = (float*)d_out;

    normalize_kernel<<<NROWS, 128>>>(emb);
    mine_kernel<<<dim3(33, NBANDS), 256>>>(labels);
    triplet_kernel<<<NROWS, 128>>>(emb);
    reduce_kernel<<<1, 256>>>(out);
}

// round 10
// speedup vs baseline: 33.3644x; 1.1205x over previous
#include <cuda_runtime.h>
#include <cuda_fp16.h>
#include <math_constants.h>
#include <cstdint>

#define NROWS 8192
#define DDIM  512
#define MTILE 128
#define NTILE 128
#define BKH 32                            // halves per k-stage
#define NSTAGES (DDIM / BKH)              // 16
#define NBANDS (NROWS / NTILE)            // 64
#define SMS 40                            // smem row stride in halves (32 + 8 pad)
#define TILE_BYTES (MTILE * SMS * 2)      // 10240
#define DYN_SMEM (6 * TILE_BYTES)         // 3 stages x (A+B) = 61440

typedef unsigned long long u64;
#define KPOS_INIT 0xFFFFFFFFFFFFFFFFull
#define KNEG_INIT 0ull

// ---------------- scratch ----------------
__device__ __half g_unith[NROWS * DDIM];  // fp16 unit vectors (8 MB, L2-resident)
__device__ u64    g_posKey[NROWS];        // min over (ord(dot)<<32 | j)
__device__ u64    g_negKey[NROWS];        // max over (ord(dot)<<32 | (~0u - j))
__device__ float  g_per[NROWS];
__device__ float  g_val[NROWS];

// ---------------- helpers ----------------
__device__ __forceinline__ uint32_t smem_u32(const void* p) {
    uint32_t a;
    asm("{ .reg .u64 t; cvta.to.shared.u64 t, %1; cvt.u32.u64 %0, t; }"
        : "=r"(a) : "l"(p));
    return a;
}

__device__ __forceinline__ void cp16(uint32_t dst, const void* src) {
    asm volatile("cp.async.cg.shared.global [%0], [%1], 16;"
                 :: "r"(dst), "l"(src));
}
#define CP_COMMIT() asm volatile("cp.async.commit_group;" ::: "memory")
#define CP_WAIT(n)  asm volatile("cp.async.wait_group %0;" :: "n"(n) : "memory")

__device__ __forceinline__ void ldm_x4(uint32_t* r, uint32_t addr) {
    asm volatile("ldmatrix.sync.aligned.m8n8.x4.shared.b16 {%0,%1,%2,%3}, [%4];"
                 : "=r"(r[0]), "=r"(r[1]), "=r"(r[2]), "=r"(r[3]) : "r"(addr));
}

// monotonic float -> uint mapping
__device__ __forceinline__ uint32_t ford(float f) {
    uint32_t u = __float_as_uint(f);
    return u ^ (uint32_t)(((int32_t)u >> 31) | 0x80000000);
}

__device__ __forceinline__ void mma_f16(float* c, const uint32_t* a,
                                        uint32_t b0, uint32_t b1) {
    asm volatile(
        "mma.sync.aligned.m16n8k16.row.col.f32.f16.f16.f32 "
        "{%0,%1,%2,%3}, {%4,%5,%6,%7}, {%8,%9}, {%0,%1,%2,%3};"
        : "+f"(c[0]), "+f"(c[1]), "+f"(c[2]), "+f"(c[3])
        : "r"(a[0]), "r"(a[1]), "r"(a[2]), "r"(a[3]), "r"(b0), "r"(b1));
}

// ---------------- kernel 1: normalize rows -> fp16, init keys ----------------
__global__ void normalize_kernel(const float* __restrict__ emb) {
    int row = blockIdx.x;
    int t   = threadIdx.x;
    float4 v = ((const float4*)(emb + (size_t)row * DDIM))[t];
    float s = v.x * v.x + v.y * v.y + v.z * v.z + v.w * v.w;
    #pragma unroll
    for (int o = 16; o; o >>= 1) s += __shfl_down_sync(0xffffffffu, s, o);
    __shared__ float ws[4];
    if ((t & 31) == 0) ws[t >> 5] = s;
    __syncthreads();
    float tot = ws[0] + ws[1] + ws[2] + ws[3];
    float inv = 1.0f / fmaxf(sqrtf(tot), 1e-8f);
    __half2* dst = (__half2*)(g_unith + (size_t)row * DDIM);
    dst[2 * t]     = __floats2half2_rn(v.x * inv, v.y * inv);
    dst[2 * t + 1] = __floats2half2_rn(v.z * inv, v.w * inv);
    if (t == 0) { g_posKey[row] = KPOS_INIT; g_negKey[row] = KNEG_INIT; }
}

// ---------------- kernel 2: fp16 mma Gram, one 128x128 tile per CTA ----------
// grid (33, 64): bi = blockIdx.y, bj = (bi + d) % 64, d = blockIdx.x.
// Upper-triangle coverage; d==32 duplicates for bi>=32 are skipped.
// 3-stage cp.async pipeline, ONE __syncthreads per k-stage.
__global__ void __launch_bounds__(256)
mine_kernel(const int* __restrict__ labels) {
    extern __shared__ __half dyn[];
    __shared__ u64 rowPos[128], rowNeg[128], colPos[128], colNeg[128];
    __shared__ int lblI[128], lblJ[128];

    const int d  = blockIdx.x;
    const int bi = blockIdx.y;
    if (d == 32 && bi >= 32) return;
    const int bj = (bi + d) & (NBANDS - 1);
    const int i0 = bi * MTILE;
    const int j0 = bj * NTILE;

    const int tid  = threadIdx.x;
    const int lane = tid & 31;
    const int wid  = tid >> 5;
    const int gid  = lane >> 2;     // 0..7
    const int tig  = lane & 3;      // 0..3
    const int wr   = wid >> 1;      // 0..3 (row band: wr*32)
    const int wc   = wid & 1;       // 0..1 (col band: wc*64)

    if (tid < 128) {
        lblI[tid] = labels[i0 + tid];
        lblJ[tid] = labels[j0 + tid];
        rowPos[tid] = KPOS_INIT; rowNeg[tid] = KNEG_INIT;
        colPos[tid] = KPOS_INIT; colNeg[tid] = KNEG_INIT;
    }
    __syncthreads();

    int myLbl[2][2];
    #pragma unroll
    for (int mi = 0; mi < 2; mi++)
        #pragma unroll
        for (int h = 0; h < 2; h++)
            myLbl[mi][h] = lblI[wr * 32 + mi * 16 + h * 8 + gid];

    const uint32_t sbase = smem_u32(dyn);
    // A buf s: sbase + s*TILE_BYTES ; B buf s: sbase + 3*TILE_BYTES + s*TILE_BYTES
    uint32_t abuf[3], bbuf[3];
    #pragma unroll
    for (int s = 0; s < 3; s++) {
        abuf[s] = sbase + s * TILE_BYTES;
        bbuf[s] = sbase + (3 + s) * TILE_BYTES;
    }

    // per-thread cp.async source/dst offsets
    const int ldrow = tid >> 2;               // 0..63 (x2 iters -> 128)
    const int ldc   = tid & 3;                // 0..3
    const uint32_t soff0 = (uint32_t)(ldrow * SMS + ldc * 8) * 2u;
    const uint32_t soff1 = (uint32_t)((ldrow + 64) * SMS + ldc * 8) * 2u;

    // ldmatrix lane address bases (in halves)
    const int lr = lane & 7;
    const int rowA = wr * 32 + ((lane >> 3) & 1) * 8 + lr;  // + mi*16
    const int kA   = (lane >> 4) * 8;                        // + kk*16
    const int nB   = wc * 64 + (lane >> 4) * 8 + lr;         // + ni2*16
    const int kB   = ((lane >> 3) & 1) * 8;                  // + kk*16

    float acc[2][8][4];
    #pragma unroll
    for (int mi = 0; mi < 2; mi++)
        #pragma unroll
        for (int ni = 0; ni < 8; ni++)
            #pragma unroll
            for (int q = 0; q < 4; q++) acc[mi][ni][q] = 0.0f;

    // ---- prologue: commit stages 0 and 1 ----
    #pragma unroll
    for (int s = 0; s < 2; s++) {
        const int k0 = s * BKH;
        cp16(abuf[s] + soff0, g_unith + (size_t)(i0 + ldrow) * DDIM + k0 + ldc * 8);
        cp16(bbuf[s] + soff0, g_unith + (size_t)(j0 + ldrow) * DDIM + k0 + ldc * 8);
        cp16(abuf[s] + soff1, g_unith + (size_t)(i0 + 64 + ldrow) * DDIM + k0 + ldc * 8);
        cp16(bbuf[s] + soff1, g_unith + (size_t)(j0 + 64 + ldrow) * DDIM + k0 + ldc * 8);
        CP_COMMIT();
    }

    int buf = 0;
    for (int s = 0; s < NSTAGES; s++) {
        CP_WAIT(1);
        __syncthreads();   // publish stage s; also: all warps done reading buf of s-1

        if (s + 2 < NSTAGES) {
            const int nb = (buf + 2 >= 3) ? buf - 1 : buf + 2;
            const int k0 = (s + 2) * BKH;
            cp16(abuf[nb] + soff0, g_unith + (size_t)(i0 + ldrow) * DDIM + k0 + ldc * 8);
            cp16(bbuf[nb] + soff0, g_unith + (size_t)(j0 + ldrow) * DDIM + k0 + ldc * 8);
            cp16(abuf[nb] + soff1, g_unith + (size_t)(i0 + 64 + ldrow) * DDIM + k0 + ldc * 8);
            cp16(bbuf[nb] + soff1, g_unith + (size_t)(j0 + 64 + ldrow) * DDIM + k0 + ldc * 8);
            CP_COMMIT();
        } else {
            CP_COMMIT();   // keep group count in lockstep for CP_WAIT(1)
        }

        const uint32_t abase = abuf[buf];
        const uint32_t bbase = bbuf[buf];
        #pragma unroll
        for (int kk = 0; kk < 2; kk++) {
            uint32_t a0[4], a1[4];
            ldm_x4(a0, abase + (uint32_t)((rowA)      * SMS + kA + kk * 16) * 2u);
            ldm_x4(a1, abase + (uint32_t)((rowA + 16) * SMS + kA + kk * 16) * 2u);
            #pragma unroll
            for (int ni2 = 0; ni2 < 4; ni2++) {
                uint32_t b[4];
                ldm_x4(b, bbase + (uint32_t)((nB + ni2 * 16) * SMS + kB + kk * 16) * 2u);
                mma_f16(acc[0][2 * ni2],     a0, b[0], b[1]);
                mma_f16(acc[0][2 * ni2 + 1], a0, b[2], b[3]);
                mma_f16(acc[1][2 * ni2],     a1, b[0], b[1]);
                mma_f16(acc[1][2 * ni2 + 1], a1, b[2], b[3]);
            }
        }
        buf = (buf + 1 >= 3) ? 0 : buf + 1;
    }

    // ---- row-side selection (rows of band bi) ----
    #pragma unroll
    for (int mi = 0; mi < 2; mi++) {
        #pragma unroll
        for (int h = 0; h < 2; h++) {
            int r   = wr * 32 + mi * 16 + h * 8 + gid;
            int gi  = i0 + r;
            int lbl = myLbl[mi][h];
            u64 pk = KPOS_INIT, nk = KNEG_INIT;
            #pragma unroll
            for (int ni = 0; ni < 8; ni++) {
                #pragma unroll
                for (int u = 0; u < 2; u++) {
                    int jc = wc * 64 + ni * 8 + tig * 2 + u;
                    int j  = j0 + jc;
                    u64 od = (u64)ford(acc[mi][ni][h * 2 + u]) << 32;
                    if (lblJ[jc] == lbl) {
                        if (j != gi) {
                            u64 k = od | (uint32_t)j;
                            if (k < pk) pk = k;
                        }
                    } else {
                        u64 k = od | (uint32_t)(0xFFFFFFFFu - j);
                        if (k > nk) nk = k;
                    }
                }
            }
            #pragma unroll
            for (int off = 2; off; off >>= 1) {
                u64 opk = __shfl_down_sync(0xffffffffu, pk, off, 4);
                u64 onk = __shfl_down_sync(0xffffffffu, nk, off, 4);
                if (opk < pk) pk = opk;
                if (onk > nk) nk = onk;
            }
            if (tig == 0) {
                if (pk != KPOS_INIT) atomicMin(&rowPos[r], pk);
                if (nk != KNEG_INIT) atomicMax(&rowNeg[r], nk);
            }
        }
    }

    // ---- column-side selection (rows of band bj, via transpose) ----
    #pragma unroll
    for (int ni = 0; ni < 8; ni++) {
        #pragma unroll
        for (int u = 0; u < 2; u++) {
            int jc = wc * 64 + ni * 8 + tig * 2 + u;
            int gj = j0 + jc;
            int lj = lblJ[jc];
            u64 pk = KPOS_INIT, nk = KNEG_INIT;
            #pragma unroll
            for (int mi = 0; mi < 2; mi++) {
                #pragma unroll
                for (int h = 0; h < 2; h++) {
                    int gi = i0 + wr * 32 + mi * 16 + h * 8 + gid;
                    u64 od = (u64)ford(acc[mi][ni][h * 2 + u]) << 32;
                    if (myLbl[mi][h] == lj) {
                        if (gi != gj) {
                            u64 k = od | (uint32_t)gi;
                            if (k < pk) pk = k;
                        }
                    } else {
                        u64 k = od | (uint32_t)(0xFFFFFFFFu - gi);
                        if (k > nk) nk = k;
                    }
                }
            }
            #pragma unroll
            for (int off = 16; off >= 4; off >>= 1) {
                u64 opk = __shfl_down_sync(0xffffffffu, pk, off);
                u64 onk = __shfl_down_sync(0xffffffffu, nk, off);
                if (opk < pk) pk = opk;
                if (onk > nk) nk = onk;
            }
            if (gid == 0) {
                if (pk != KPOS_INIT) atomicMin(&colPos[jc], pk);
                if (nk != KNEG_INIT) atomicMax(&colNeg[jc], nk);
            }
        }
    }
    __syncthreads();

    // ---- flush both bands (min/max idempotent -> diagonal overlap is safe) ----
    if (tid < 128) {
        u64 rp = rowPos[tid], rn = rowNeg[tid];
        u64 cp = colPos[tid], cn = colNeg[tid];
        if (rp != KPOS_INIT) atomicMin(&g_posKey[i0 + tid], rp);
        if (rn != KNEG_INIT) atomicMax(&g_negKey[i0 + tid], rn);
        if (cp != KPOS_INIT) atomicMin(&g_posKey[j0 + tid], cp);
        if (cn != KNEG_INIT) atomicMax(&g_negKey[j0 + tid], cn);
    }
}

// ---------------- kernel 3: per-row triplet loss ----------------
__global__ void triplet_kernel(const float* __restrict__ emb) {
    int i = blockIdx.x;
    int t = threadIdx.x;

    __shared__ int spi, sni;
    __shared__ bool svalid;
    if (t == 0) {
        u64 pk = g_posKey[i];
        u64 nk = g_negKey[i];
        spi = (int)(uint32_t)(pk & 0xFFFFFFFFull);
        sni = (int)(0xFFFFFFFFu - (uint32_t)(nk & 0xFFFFFFFFull));
        svalid = (pk != KPOS_INIT) && (nk != KNEG_INIT);
    }
    __syncthreads();
    if (!svalid) {
        if (t == 0) { g_per[i] = 0.0f; g_val[i] = 0.0f; }
        return;
    }
    int pi = spi, ni = sni;
    float4 av = ((const float4*)(emb + (size_t)i  * DDIM))[t];
    float4 pv = ((const float4*)(emb + (size_t)pi * DDIM))[t];
    float4 nv = ((const float4*)(emb + (size_t)ni * DDIM))[t];

    float sap = 0.0f, san = 0.0f, dd;
    dd = av.x - pv.x + 1e-6f; sap += dd * dd;
    dd = av.y - pv.y + 1e-6f; sap += dd * dd;
    dd = av.z - pv.z + 1e-6f; sap += dd * dd;
    dd = av.w - pv.w + 1e-6f; sap += dd * dd;
    dd = av.x - nv.x + 1e-6f; san += dd * dd;
    dd = av.y - nv.y + 1e-6f; san += dd * dd;
    dd = av.z - nv.z + 1e-6f; san += dd * dd;
    dd = av.w - nv.w + 1e-6f; san += dd * dd;

    #pragma unroll
    for (int o = 16; o; o >>= 1) {
        sap += __shfl_down_sync(0xffffffffu, sap, o);
        san += __shfl_down_sync(0xffffffffu, san, o);
    }
    __shared__ float wp[4], wn[4];
    if ((t & 31) == 0) { wp[t >> 5] = sap; wn[t >> 5] = san; }
    __syncthreads();
    if (t == 0) {
        float tp = wp[0] + wp[1] + wp[2] + wp[3];
        float tn = wn[0] + wn[1] + wn[2] + wn[3];
        float l  = sqrtf(tp) - sqrtf(tn) + 1.0f;   // margin = 1.0
        g_per[i] = fmaxf(l, 0.0f);
        g_val[i] = 1.0f;
    }
}

// ---------------- kernel 4: deterministic final reduction ----------------
__global__ void reduce_kernel(float* __restrict__ out) {
    int t = threadIdx.x;
    float s = 0.0f, c = 0.0f;
    for (int i = t; i < NROWS; i += 1024) { s += g_per[i]; c += g_val[i]; }
    #pragma unroll
    for (int o = 16; o; o >>= 1) {
        s += __shfl_down_sync(0xffffffffu, s, o);
        c += __shfl_down_sync(0xffffffffu, c, o);
    }
    __shared__ float ss[32], sc[32];
    if ((t & 31) == 0) { ss[t >> 5] = s; sc[t >> 5] = c; }
    __syncthreads();
    if (t < 32) {
        s = ss[t]; c = sc[t];
        #pragma unroll
        for (int o = 16; o; o >>= 1) {
            s += __shfl_down_sync(0xffffffffu, s, o);
            c += __shfl_down_sync(0xffffffffu, c, o);
        }
        if (t == 0) out[0] = s / fmaxf(c, 1.0f);
    }
}

// ---------------- launch ----------------
extern "C" void kernel_launch(void* const* d_in, const int* in_sizes, int n_in,
                              void* d_out, int out_size) {
    const float* emb    = (const float*)d_in[0];
    const int*   labels = (const int*)d_in[1];
    float*       out    = (float*)d_out;

    cudaFuncSetAttribute(mine_kernel,
                         cudaFuncAttributeMaxDynamicSharedMemorySize, DYN_SMEM);

    normalize_kernel<<<NROWS, 128>>>(emb);
    mine_kernel<<<dim3(33, NBANDS), 256, DYN_SMEM>>>(labels);
    triplet_kernel<<<NROWS, 128>>>(emb);
    reduce_kernel<<<1, 1024>>>(out);
}

// round 11
// speedup vs baseline: 34.0824x; 1.0215x over previous
#include <cuda_runtime.h>
#include <cuda_fp16.h>
#include <math_constants.h>
#include <cstdint>

#define NROWS 8192
#define DDIM  512
#define MTILE 128
#define NTILE 128
#define BKH 64                            // halves per k-stage
#define NSTAGES (DDIM / BKH)              // 8
#define NBANDS (NROWS / NTILE)            // 64
#define SMS 72                            // smem row stride in halves (64 + 8 pad)
#define TILE_BYTES (MTILE * SMS * 2)      // 18432
#define DYN_SMEM (6 * TILE_BYTES)         // 3 stages x (A+B) = 110592

typedef unsigned long long u64;
#define KPOS_INIT 0xFFFFFFFFFFFFFFFFull
#define KNEG_INIT 0ull

// ---------------- scratch ----------------
__device__ __half g_unith[NROWS * DDIM];  // fp16 unit vectors (8 MB, L2-resident)
__device__ u64    g_posKey[NROWS];        // min over (ord(dot)<<32 | j)
__device__ u64    g_negKey[NROWS];        // max over (ord(dot)<<32 | (~0u - j))
__device__ u64    g_sumFix;               // sum(loss * 2^32), order-independent
__device__ unsigned int g_cnt;
__device__ unsigned int g_done;

// ---------------- helpers ----------------
__device__ __forceinline__ uint32_t smem_u32(const void* p) {
    uint32_t a;
    asm("{ .reg .u64 t; cvta.to.shared.u64 t, %1; cvt.u32.u64 %0, t; }"
        : "=r"(a) : "l"(p));
    return a;
}

__device__ __forceinline__ void cp16(uint32_t dst, const void* src) {
    asm volatile("cp.async.cg.shared.global [%0], [%1], 16;"
                 :: "r"(dst), "l"(src));
}
#define CP_COMMIT() asm volatile("cp.async.commit_group;" ::: "memory")
#define CP_WAIT(n)  asm volatile("cp.async.wait_group %0;" :: "n"(n) : "memory")

__device__ __forceinline__ void ldm_x4(uint32_t* r, uint32_t addr) {
    asm volatile("ldmatrix.sync.aligned.m8n8.x4.shared.b16 {%0,%1,%2,%3}, [%4];"
                 : "=r"(r[0]), "=r"(r[1]), "=r"(r[2]), "=r"(r[3]) : "r"(addr));
}

// monotonic float -> uint mapping
__device__ __forceinline__ uint32_t ford(float f) {
    uint32_t u = __float_as_uint(f);
    return u ^ (uint32_t)(((int32_t)u >> 31) | 0x80000000);
}

__device__ __forceinline__ void mma_f16(float* c, const uint32_t* a,
                                        uint32_t b0, uint32_t b1) {
    asm volatile(
        "mma.sync.aligned.m16n8k16.row.col.f32.f16.f16.f32 "
        "{%0,%1,%2,%3}, {%4,%5,%6,%7}, {%8,%9}, {%0,%1,%2,%3};"
        : "+f"(c[0]), "+f"(c[1]), "+f"(c[2]), "+f"(c[3])
        : "r"(a[0]), "r"(a[1]), "r"(a[2]), "r"(a[3]), "r"(b0), "r"(b1));
}

// ---------------- kernel 1: normalize rows -> fp16, init keys + accumulators --
__global__ void normalize_kernel(const float* __restrict__ emb) {
    int row = blockIdx.x;
    int t   = threadIdx.x;
    float4 v = ((const float4*)(emb + (size_t)row * DDIM))[t];
    float s = v.x * v.x + v.y * v.y + v.z * v.z + v.w * v.w;
    #pragma unroll
    for (int o = 16; o; o >>= 1) s += __shfl_down_sync(0xffffffffu, s, o);
    __shared__ float ws[4];
    if ((t & 31) == 0) ws[t >> 5] = s;
    __syncthreads();
    float tot = ws[0] + ws[1] + ws[2] + ws[3];
    float inv = 1.0f / fmaxf(sqrtf(tot), 1e-8f);
    __half2* dst = (__half2*)(g_unith + (size_t)row * DDIM);
    dst[2 * t]     = __floats2half2_rn(v.x * inv, v.y * inv);
    dst[2 * t + 1] = __floats2half2_rn(v.z * inv, v.w * inv);
    if (t == 0) {
        g_posKey[row] = KPOS_INIT;
        g_negKey[row] = KNEG_INIT;
        if (row == 0) { g_sumFix = 0ull; g_cnt = 0u; g_done = 0u; }
    }
}

// ---------------- kernel 2: fp16 mma Gram, one 128x128 tile per CTA ----------
// grid (33, 64): bi = blockIdx.y, bj = (bi + d) % 64, d = blockIdx.x.
// Upper-triangle coverage; d==32 duplicates for bi>=32 are skipped.
// 3-stage cp.async pipeline (K=64/stage), ONE __syncthreads per k-stage.
__global__ void __launch_bounds__(256)
mine_kernel(const int* __restrict__ labels) {
    extern __shared__ __half dyn[];
    __shared__ u64 rowPos[128], rowNeg[128], colPos[128], colNeg[128];
    __shared__ int lblI[128], lblJ[128];

    const int d  = blockIdx.x;
    const int bi = blockIdx.y;
    if (d == 32 && bi >= 32) return;
    const int bj = (bi + d) & (NBANDS - 1);
    const int i0 = bi * MTILE;
    const int j0 = bj * NTILE;

    const int tid  = threadIdx.x;
    const int lane = tid & 31;
    const int wid  = tid >> 5;
    const int gid  = lane >> 2;     // 0..7
    const int tig  = lane & 3;      // 0..3
    const int wr   = wid >> 1;      // 0..3 (row band: wr*32)
    const int wc   = wid & 1;       // 0..1 (col band: wc*64)

    if (tid < 128) {
        lblI[tid] = labels[i0 + tid];
        lblJ[tid] = labels[j0 + tid];
        rowPos[tid] = KPOS_INIT; rowNeg[tid] = KNEG_INIT;
        colPos[tid] = KPOS_INIT; colNeg[tid] = KNEG_INIT;
    }
    __syncthreads();

    int myLbl[2][2];
    #pragma unroll
    for (int mi = 0; mi < 2; mi++)
        #pragma unroll
        for (int h = 0; h < 2; h++)
            myLbl[mi][h] = lblI[wr * 32 + mi * 16 + h * 8 + gid];

    const uint32_t sbase = smem_u32(dyn);
    uint32_t abuf[3], bbuf[3];
    #pragma unroll
    for (int s = 0; s < 3; s++) {
        abuf[s] = sbase + s * TILE_BYTES;
        bbuf[s] = sbase + (3 + s) * TILE_BYTES;
    }

    // per-thread cp.async offsets: 256 threads = 32 rows x 8 cols of 16B
    const int ldrow = tid >> 3;               // 0..31 (x4 iters -> 128 rows)
    const int ldc   = tid & 7;                // 0..7  (8 x 8 halves = 64)
    uint32_t soff[4];
    #pragma unroll
    for (int it = 0; it < 4; it++)
        soff[it] = (uint32_t)((ldrow + it * 32) * SMS + ldc * 8) * 2u;

    // ldmatrix lane address bases (in halves)
    const int lr = lane & 7;
    const int rowA = wr * 32 + ((lane >> 3) & 1) * 8 + lr;  // + mi*16
    const int kA   = (lane >> 4) * 8;                        // + kk*16
    const int nB   = wc * 64 + (lane >> 4) * 8 + lr;         // + ni2*16
    const int kB   = ((lane >> 3) & 1) * 8;                  // + kk*16

    float acc[2][8][4];
    #pragma unroll
    for (int mi = 0; mi < 2; mi++)
        #pragma unroll
        for (int ni = 0; ni < 8; ni++)
            #pragma unroll
            for (int q = 0; q < 4; q++) acc[mi][ni][q] = 0.0f;

    // ---- prologue: commit stages 0 and 1 ----
    #pragma unroll
    for (int s = 0; s < 2; s++) {
        const int k0 = s * BKH;
        #pragma unroll
        for (int it = 0; it < 4; it++) {
            cp16(abuf[s] + soff[it], g_unith + (size_t)(i0 + ldrow + it * 32) * DDIM + k0 + ldc * 8);
            cp16(bbuf[s] + soff[it], g_unith + (size_t)(j0 + ldrow + it * 32) * DDIM + k0 + ldc * 8);
        }
        CP_COMMIT();
    }

    int buf = 0;
    for (int s = 0; s < NSTAGES; s++) {
        CP_WAIT(1);
        __syncthreads();   // publish stage s; all warps done reading buf of s-1

        if (s + 2 < NSTAGES) {
            const int nb = (buf + 2 >= 3) ? buf - 1 : buf + 2;
            const int k0 = (s + 2) * BKH;
            #pragma unroll
            for (int it = 0; it < 4; it++) {
                cp16(abuf[nb] + soff[it], g_unith + (size_t)(i0 + ldrow + it * 32) * DDIM + k0 + ldc * 8);
                cp16(bbuf[nb] + soff[it], g_unith + (size_t)(j0 + ldrow + it * 32) * DDIM + k0 + ldc * 8);
            }
            CP_COMMIT();
        } else {
            CP_COMMIT();   // keep group count in lockstep for CP_WAIT(1)
        }

        const uint32_t abase = abuf[buf];
        const uint32_t bbase = bbuf[buf];
        #pragma unroll
        for (int kk = 0; kk < 4; kk++) {
            uint32_t a0[4], a1[4];
            ldm_x4(a0, abase + (uint32_t)((rowA)      * SMS + kA + kk * 16) * 2u);
            ldm_x4(a1, abase + (uint32_t)((rowA + 16) * SMS + kA + kk * 16) * 2u);
            #pragma unroll
            for (int ni2 = 0; ni2 < 4; ni2++) {
                uint32_t b[4];
                ldm_x4(b, bbase + (uint32_t)((nB + ni2 * 16) * SMS + kB + kk * 16) * 2u);
                mma_f16(acc[0][2 * ni2],     a0, b[0], b[1]);
                mma_f16(acc[0][2 * ni2 + 1], a0, b[2], b[3]);
                mma_f16(acc[1][2 * ni2],     a1, b[0], b[1]);
                mma_f16(acc[1][2 * ni2 + 1], a1, b[2], b[3]);
            }
        }
        buf = (buf + 1 >= 3) ? 0 : buf + 1;
    }

    // ---- row-side selection (rows of band bi) ----
    #pragma unroll
    for (int mi = 0; mi < 2; mi++) {
        #pragma unroll
        for (int h = 0; h < 2; h++) {
            int r   = wr * 32 + mi * 16 + h * 8 + gid;
            int gi  = i0 + r;
            int lbl = myLbl[mi][h];
            u64 pk = KPOS_INIT, nk = KNEG_INIT;
            #pragma unroll
            for (int ni = 0; ni < 8; ni++) {
                #pragma unroll
                for (int u = 0; u < 2; u++) {
                    int jc = wc * 64 + ni * 8 + tig * 2 + u;
                    int j  = j0 + jc;
                    u64 od = (u64)ford(acc[mi][ni][h * 2 + u]) << 32;
                    if (lblJ[jc] == lbl) {
                        if (j != gi) {
                            u64 k = od | (uint32_t)j;
                            if (k < pk) pk = k;
                        }
                    } else {
                        u64 k = od | (uint32_t)(0xFFFFFFFFu - j);
                        if (k > nk) nk = k;
                    }
                }
            }
            #pragma unroll
            for (int off = 2; off; off >>= 1) {
                u64 opk = __shfl_down_sync(0xffffffffu, pk, off, 4);
                u64 onk = __shfl_down_sync(0xffffffffu, nk, off, 4);
                if (opk < pk) pk = opk;
                if (onk > nk) nk = onk;
            }
            if (tig == 0) {
                if (pk != KPOS_INIT) atomicMin(&rowPos[r], pk);
                if (nk != KNEG_INIT) atomicMax(&rowNeg[r], nk);
            }
        }
    }

    // ---- column-side selection (rows of band bj, via transpose) ----
    #pragma unroll
    for (int ni = 0; ni < 8; ni++) {
        #pragma unroll
        for (int u = 0; u < 2; u++) {
            int jc = wc * 64 + ni * 8 + tig * 2 + u;
            int gj = j0 + jc;
            int lj = lblJ[jc];
            u64 pk = KPOS_INIT, nk = KNEG_INIT;
            #pragma unroll
            for (int mi = 0; mi < 2; mi++) {
                #pragma unroll
                for (int h = 0; h < 2; h++) {
                    int gi = i0 + wr * 32 + mi * 16 + h * 8 + gid;
                    u64 od = (u64)ford(acc[mi][ni][h * 2 + u]) << 32;
                    if (myLbl[mi][h] == lj) {
                        if (gi != gj) {
                            u64 k = od | (uint32_t)gi;
                            if (k < pk) pk = k;
                        }
                    } else {
                        u64 k = od | (uint32_t)(0xFFFFFFFFu - gi);
                        if (k > nk) nk = k;
                    }
                }
            }
            #pragma unroll
            for (int off = 16; off >= 4; off >>= 1) {
                u64 opk = __shfl_down_sync(0xffffffffu, pk, off);
                u64 onk = __shfl_down_sync(0xffffffffu, nk, off);
                if (opk < pk) pk = opk;
                if (onk > nk) nk = onk;
            }
            if (gid == 0) {
                if (pk != KPOS_INIT) atomicMin(&colPos[jc], pk);
                if (nk != KNEG_INIT) atomicMax(&colNeg[jc], nk);
            }
        }
    }
    __syncthreads();

    // ---- flush both bands (min/max idempotent -> diagonal overlap is safe) ----
    if (tid < 128) {
        u64 rp = rowPos[tid], rn = rowNeg[tid];
        u64 cp = colPos[tid], cn = colNeg[tid];
        if (rp != KPOS_INIT) atomicMin(&g_posKey[i0 + tid], rp);
        if (rn != KNEG_INIT) atomicMax(&g_negKey[i0 + tid], rn);
        if (cp != KPOS_INIT) atomicMin(&g_posKey[j0 + tid], cp);
        if (cn != KNEG_INIT) atomicMax(&g_negKey[j0 + tid], cn);
    }
}

// ---------------- kernel 3: per-row triplet loss + fused reduction ----------
// Fixed-point atomic accumulation (order-independent -> deterministic).
__global__ void triplet_kernel(const float* __restrict__ emb, float* __restrict__ out) {
    int i = blockIdx.x;
    int t = threadIdx.x;

    __shared__ int spi, sni;
    __shared__ bool svalid;
    if (t == 0) {
        u64 pk = g_posKey[i];
        u64 nk = g_negKey[i];
        spi = (int)(uint32_t)(pk & 0xFFFFFFFFull);
        sni = (int)(0xFFFFFFFFu - (uint32_t)(nk & 0xFFFFFFFFull));
        svalid = (pk != KPOS_INIT) && (nk != KNEG_INIT);
    }
    __syncthreads();

    float loss = 0.0f;
    bool valid = svalid;
    if (valid) {
        int pi = spi, ni = sni;
        float4 av = ((const float4*)(emb + (size_t)i  * DDIM))[t];
        float4 pv = ((const float4*)(emb + (size_t)pi * DDIM))[t];
        float4 nv = ((const float4*)(emb + (size_t)ni * DDIM))[t];

        float sap = 0.0f, san = 0.0f, dd;
        dd = av.x - pv.x + 1e-6f; sap += dd * dd;
        dd = av.y - pv.y + 1e-6f; sap += dd * dd;
        dd = av.z - pv.z + 1e-6f; sap += dd * dd;
        dd = av.w - pv.w + 1e-6f; sap += dd * dd;
        dd = av.x - nv.x + 1e-6f; san += dd * dd;
        dd = av.y - nv.y + 1e-6f; san += dd * dd;
        dd = av.z - nv.z + 1e-6f; san += dd * dd;
        dd = av.w - nv.w + 1e-6f; san += dd * dd;

        #pragma unroll
        for (int o = 16; o; o >>= 1) {
            sap += __shfl_down_sync(0xffffffffu, sap, o);
            san += __shfl_down_sync(0xffffffffu, san, o);
        }
        __shared__ float wp[4], wn[4];
        if ((t & 31) == 0) { wp[t >> 5] = sap; wn[t >> 5] = san; }
        __syncthreads();
        if (t == 0) {
            float tp = wp[0] + wp[1] + wp[2] + wp[3];
            float tn = wn[0] + wn[1] + wn[2] + wn[3];
            loss = fmaxf(sqrtf(tp) - sqrtf(tn) + 1.0f, 0.0f);   // margin = 1.0
        }
    }

    if (t == 0) {
        if (valid) {
            u64 fx = (u64)__double2ll_rn((double)loss * 4294967296.0);
            atomicAdd(&g_sumFix, fx);
            atomicAdd(&g_cnt, 1u);
        }
        __threadfence();
        unsigned int ticket = atomicAdd(&g_done, 1u);
        if (ticket == gridDim.x - 1) {
            double s = (double)g_sumFix / 4294967296.0;
            float  c = (float)g_cnt;
            out[0] = (float)(s / (double)fmaxf(c, 1.0f));
        }
    }
}

// ---------------- launch ----------------
extern "C" void kernel_launch(void* const* d_in, const int* in_sizes, int n_in,
                              void* d_out, int out_size) {
    const float* emb    = (const float*)d_in[0];
    const int*   labels = (const int*)d_in[1];
    float*       out    = (float*)d_out;

    cudaFuncSetAttribute(mine_kernel,
                         cudaFuncAttributeMaxDynamicSharedMemorySize, DYN_SMEM);

    normalize_kernel<<<NROWS, 128>>>(emb);
    mine_kernel<<<dim3(33, NBANDS), 256, DYN_SMEM>>>(labels);
    triplet_kernel<<<NROWS, 128>>>(emb, out);
}